// round 11
// baseline (speedup 1.0000x reference)
#include <cuda_runtime.h>
#include <cuda.h>
#include <cuda_bf16.h>
#include <math.h>
#include <stdint.h>

#define SEQ   3072
#define HDIM  1024
#define NHEAD 16
#define HEADD 64
#define MDIM  4096

// ---------------- scratch (static device globals; no allocation) ----------------
__device__ float g_x   [(size_t)SEQ * HDIM];
__device__ float g_qkv [(size_t)SEQ * 3 * HDIM];
__device__ __nv_bfloat16 g_hh[(size_t)SEQ * HDIM], g_hl[(size_t)SEQ * HDIM];
__device__ __nv_bfloat16 g_oh[(size_t)SEQ * HDIM], g_ol[(size_t)SEQ * HDIM];
__device__ __nv_bfloat16 g_qhh[(size_t)SEQ * HDIM], g_qll[(size_t)SEQ * HDIM];
__device__ __nv_bfloat16 g_khh[(size_t)SEQ * HDIM], g_kll[(size_t)SEQ * HDIM];
__device__ __nv_bfloat16 g_vhh[(size_t)SEQ * HDIM], g_vll[(size_t)SEQ * HDIM];
__device__ __nv_bfloat16 g_mh[(size_t)SEQ * MDIM], g_ml[(size_t)SEQ * MDIM];
#define WTOT 25165824
__device__ __nv_bfloat16 g_wh[WTOT], g_wl[WTOT];
__device__ float g_cos [(size_t)SEQ * 32];
__device__ float g_sin [(size_t)SEQ * 32];
__device__ int   g_bounds[17];
__device__ int   g_nseg;

// ---------------- generic helpers ----------------
__device__ __forceinline__ void mma_bf16(float* c, const uint32_t* a, const uint32_t* b) {
    asm volatile(
        "mma.sync.aligned.m16n8k16.row.col.f32.bf16.bf16.f32 "
        "{%0,%1,%2,%3}, {%4,%5,%6,%7}, {%8,%9}, {%0,%1,%2,%3};"
        : "+f"(c[0]), "+f"(c[1]), "+f"(c[2]), "+f"(c[3])
        : "r"(a[0]), "r"(a[1]), "r"(a[2]), "r"(a[3]), "r"(b[0]), "r"(b[1]));
}
__device__ __forceinline__ void ldm_x4(uint32_t* r, uint32_t addr) {
    asm volatile("ldmatrix.sync.aligned.m8n8.x4.shared.b16 {%0,%1,%2,%3}, [%4];"
        : "=r"(r[0]), "=r"(r[1]), "=r"(r[2]), "=r"(r[3]) : "r"(addr));
}
__device__ __forceinline__ void ldm_x4_t(uint32_t* r, uint32_t addr) {
    asm volatile("ldmatrix.sync.aligned.m8n8.x4.trans.shared.b16 {%0,%1,%2,%3}, [%4];"
        : "=r"(r[0]), "=r"(r[1]), "=r"(r[2]), "=r"(r[3]) : "r"(addr));
}
__device__ __forceinline__ void stm_x4(uint32_t addr, const uint32_t* r) {
    asm volatile("stmatrix.sync.aligned.m8n8.x4.shared.b16 [%0], {%1,%2,%3,%4};"
        :: "r"(addr), "r"(r[0]), "r"(r[1]), "r"(r[2]), "r"(r[3]) : "memory");
}
__device__ __forceinline__ void cp16(uint32_t smem_addr, const void* gptr) {
    asm volatile("cp.async.cg.shared.global [%0], [%1], 16;" :: "r"(smem_addr), "l"(gptr));
}
__device__ __forceinline__ void split_bf16(float v, __nv_bfloat16& h, __nv_bfloat16& l) {
    h = __float2bfloat16(v);
    l = __float2bfloat16(v - __bfloat162float(h));
}
__device__ __forceinline__ float ex2f(float x) {
    float r;
    asm("ex2.approx.ftz.f32 %0, %1;" : "=f"(r) : "f"(x));
    return r;
}
__device__ __forceinline__ uint32_t pack_bf16_hi(float a, float b, uint32_t& lo) {
    __nv_bfloat16 h0, l0, h1, l1;
    split_bf16(a, h0, l0);
    split_bf16(b, h1, l1);
    __nv_bfloat162 ph, pl;
    ph.x = h0; ph.y = h1;
    pl.x = l0; pl.y = l1;
    lo = *(uint32_t*)&pl;
    return *(uint32_t*)&ph;
}
__device__ __forceinline__ uint32_t elect_one() {
    uint32_t pred;
    asm volatile("{\n\t.reg .pred p;\n\telect.sync _|p, 0xFFFFFFFF;\n\tselp.b32 %0, 1, 0, p;\n\t}"
        : "=r"(pred));
    return pred;
}
__device__ __forceinline__ void mbar_init(uint32_t addr, uint32_t cnt) {
    asm volatile("mbarrier.init.shared.b64 [%0], %1;" :: "r"(addr), "r"(cnt) : "memory");
}
__device__ __forceinline__ void mbar_inval(uint32_t addr) {
    asm volatile("mbarrier.inval.shared.b64 [%0];" :: "r"(addr) : "memory");
}
__device__ __forceinline__ void mbar_wait(uint32_t addr, uint32_t parity) {
    asm volatile(
        "{\n\t.reg .pred P;\n\t"
        "W%=:\n\t"
        "mbarrier.try_wait.parity.acquire.cta.shared::cta.b64 P, [%0], %1, 0x989680;\n\t"
        "@!P bra W%=;\n\t}"
        :: "r"(addr), "r"(parity) : "memory");
}
__device__ __forceinline__ void mbar_expect_tx(uint32_t addr, uint32_t bytes) {
    asm volatile("mbarrier.arrive.expect_tx.shared.b64 _, [%0], %1;"
        :: "r"(addr), "r"(bytes) : "memory");
}
__device__ __forceinline__ void fence_proxy_async_s() {
    asm volatile("fence.proxy.async.shared::cta;" ::: "memory");
}
__device__ __forceinline__ void tma2d(uint32_t dst, const CUtensorMap* m, int x, int y, uint32_t mbar) {
    asm volatile(
        "cp.async.bulk.tensor.2d.shared::cta.global.tile.mbarrier::complete_tx::bytes "
        "[%0], [%1, {%2, %3}], [%4];"
        :: "r"(dst), "l"(m), "r"(x), "r"(y), "r"(mbar) : "memory");
}

// ---------------- tcgen05 helpers (bodies exist only in sm_103a pass) ----------------
#if defined(__CUDA_ARCH__) && defined(__CUDA_ARCH_FEAT_SM103_ALL)
#define TC_OK 1
#else
#define TC_OK 0
#endif

__device__ __forceinline__ void tc_mma(uint32_t d, uint64_t ad, uint64_t bd, uint32_t idesc, uint32_t en) {
#if TC_OK
    asm volatile(
        "{\n\t.reg .pred p;\n\t"
        "setp.ne.u32 p, %5, 0;\n\t"
        "tcgen05.mma.cta_group::1.kind::f16 [%0], %1, %2, %3, {%4, %4, %4, %4}, p;\n\t}"
        :: "r"(d), "l"(ad), "l"(bd), "r"(idesc), "r"(0u), "r"(en) : "memory");
#endif
}
__device__ __forceinline__ void tc_mma_ts(uint32_t d, uint32_t a_tmem, uint64_t bd, uint32_t idesc, uint32_t en) {
#if TC_OK
    asm volatile(
        "{\n\t.reg .pred p;\n\t"
        "setp.ne.u32 p, %5, 0;\n\t"
        "tcgen05.mma.cta_group::1.kind::f16 [%0], [%1], %2, %3, {%4, %4, %4, %4}, p;\n\t}"
        :: "r"(d), "r"(a_tmem), "l"(bd), "r"(idesc), "r"(0u), "r"(en) : "memory");
#endif
}
__device__ __forceinline__ void tc_commit(uint32_t mbar) {
#if TC_OK
    asm volatile(
        "tcgen05.commit.cta_group::1.mbarrier::arrive::one.shared::cluster.b64 [%0];"
        :: "r"(mbar) : "memory");
#endif
}
__device__ __forceinline__ void tc_alloc(uint32_t dst_smem, uint32_t ncols) {
#if TC_OK
    asm volatile("tcgen05.alloc.cta_group::1.sync.aligned.shared::cta.b32 [%0], %1;"
        :: "r"(dst_smem), "r"(ncols) : "memory");
#endif
}
__device__ __forceinline__ void tc_dealloc(uint32_t tmem, uint32_t ncols) {
#if TC_OK
    asm volatile("tcgen05.dealloc.cta_group::1.sync.aligned.b32 %0, %1;" :: "r"(tmem), "r"(ncols));
#endif
}
__device__ __forceinline__ void tc_relinq() {
#if TC_OK
    asm volatile("tcgen05.relinquish_alloc_permit.cta_group::1.sync.aligned;");
#endif
}
__device__ __forceinline__ void ldtm_x32(uint32_t* r, uint32_t tmem) {
#if TC_OK
    asm volatile(
        "tcgen05.ld.sync.aligned.32x32b.x32.b32 "
        "{%0, %1, %2, %3, %4, %5, %6, %7, "
        " %8, %9, %10, %11, %12, %13, %14, %15, "
        " %16, %17, %18, %19, %20, %21, %22, %23, "
        " %24, %25, %26, %27, %28, %29, %30, %31}, [%32];"
        : "=r"(r[0]),  "=r"(r[1]),  "=r"(r[2]),  "=r"(r[3]),
          "=r"(r[4]),  "=r"(r[5]),  "=r"(r[6]),  "=r"(r[7]),
          "=r"(r[8]),  "=r"(r[9]),  "=r"(r[10]), "=r"(r[11]),
          "=r"(r[12]), "=r"(r[13]), "=r"(r[14]), "=r"(r[15]),
          "=r"(r[16]), "=r"(r[17]), "=r"(r[18]), "=r"(r[19]),
          "=r"(r[20]), "=r"(r[21]), "=r"(r[22]), "=r"(r[23]),
          "=r"(r[24]), "=r"(r[25]), "=r"(r[26]), "=r"(r[27]),
          "=r"(r[28]), "=r"(r[29]), "=r"(r[30]), "=r"(r[31])
        : "r"(tmem));
#endif
}
__device__ __forceinline__ void sttm_x32(uint32_t tmem, const uint32_t* r) {
#if TC_OK
    asm volatile(
        "tcgen05.st.sync.aligned.32x32b.x32.b32 [%0], "
        "{%1, %2, %3, %4, %5, %6, %7, %8, "
        " %9, %10, %11, %12, %13, %14, %15, %16, "
        " %17, %18, %19, %20, %21, %22, %23, %24, "
        " %25, %26, %27, %28, %29, %30, %31, %32};"
        :: "r"(tmem),
           "r"(r[0]),  "r"(r[1]),  "r"(r[2]),  "r"(r[3]),
           "r"(r[4]),  "r"(r[5]),  "r"(r[6]),  "r"(r[7]),
           "r"(r[8]),  "r"(r[9]),  "r"(r[10]), "r"(r[11]),
           "r"(r[12]), "r"(r[13]), "r"(r[14]), "r"(r[15]),
           "r"(r[16]), "r"(r[17]), "r"(r[18]), "r"(r[19]),
           "r"(r[20]), "r"(r[21]), "r"(r[22]), "r"(r[23]),
           "r"(r[24]), "r"(r[25]), "r"(r[26]), "r"(r[27]),
           "r"(r[28]), "r"(r[29]), "r"(r[30]), "r"(r[31])
        : "memory");
#endif
}
__device__ __forceinline__ void tc_wait_ld() {
#if TC_OK
    asm volatile("tcgen05.wait::ld.sync.aligned;" ::: "memory");
#endif
}
__device__ __forceinline__ void tc_wait_st() {
#if TC_OK
    asm volatile("tcgen05.wait::st.sync.aligned;" ::: "memory");
#endif
}
__device__ __forceinline__ void tc_fence_after() {
#if TC_OK
    asm volatile("tcgen05.fence::after_thread_sync;" ::: "memory");
#endif
}
__device__ __forceinline__ void tc_fence_before() {
#if TC_OK
    asm volatile("tcgen05.fence::before_thread_sync;" ::: "memory");
#endif
}

// ---------------- probe: static smem marker present only when tcgen05 NOT available ----
__global__ void probe_kernel(int* out) {
#if !(defined(__CUDA_ARCH__) && defined(__CUDA_ARCH_FEAT_SM103_ALL))
    __shared__ int marker[64];
    marker[threadIdx.x & 63] = (int)threadIdx.x;
    __syncthreads();
    if (out) *out = marker[0];
#endif
}

// ---------------- setup: segment boundaries from grid_thws ----------------
__global__ void setup_kernel(const int* __restrict__ grid_thws, int ngrids) {
    if (threadIdx.x == 0 && blockIdx.x == 0) {
        int acc = 0;
        g_bounds[0] = 0;
        for (int g = 0; g < ngrids; g++) {
            acc += grid_thws[3*g] * grid_thws[3*g+1] * grid_thws[3*g+2];
            g_bounds[g+1] = acc;
        }
        g_nseg = ngrids;
    }
}

// ---------------- rope tables ----------------
__global__ void cossin_kernel(const int* __restrict__ grid_thws, int ngrids, int S) {
    int idx = blockIdx.x * blockDim.x + threadIdx.x;
    if (idx >= S * 32) return;
    int s = idx >> 5;
    int p = idx & 31;
    int start = 0, t = 1, h = 1, w = 1, local = 0;
    for (int g = 0; g < ngrids; g++) {
        t = grid_thws[3*g]; h = grid_thws[3*g+1]; w = grid_thws[3*g+2];
        int len = t * h * w;
        if (s < start + len) { local = s - start; break; }
        start += len;
    }
    int hw  = h * w;
    int rem = local % hw;
    int ys  = rem / w;
    int xs  = rem % w;
    int f   = p >> 1;
    double freq = pow(10000.0, -(double)(4 * f) / 64.0);
    double pos  = (p & 1) ? (double)ys : (double)xs;
    double ang  = pos * freq;
    g_cos[idx] = (float)cos(ang);
    g_sin[idx] = (float)sin(ang);
}

// ---------------- weight conversion fp32 -> bf16 hi/lo (2 sources per launch) ---
__global__ void conv2_kernel(const float* __restrict__ s1, __nv_bfloat16* __restrict__ dh1,
                             __nv_bfloat16* __restrict__ dl1, int n1,
                             const float* __restrict__ s2, __nv_bfloat16* __restrict__ dh2,
                             __nv_bfloat16* __restrict__ dl2, int n2) {
    int i = blockIdx.x * 256 + threadIdx.x;
    const float* s;
    __nv_bfloat16 *dh, *dl;
    if (i < n1) { s = s1; dh = dh1; dl = dl1; }
    else {
        i -= n1;
        if (i >= n2) return;
        s = s2; dh = dh2; dl = dl2;
    }
    float4 v = ((const float4*)s)[i];
    __nv_bfloat16 h0, h1, h2, h3, l0, l1, l2, l3;
    split_bf16(v.x, h0, l0); split_bf16(v.y, h1, l1);
    split_bf16(v.z, h2, l2); split_bf16(v.w, h3, l3);
    __nv_bfloat162 a, b;
    a.x = h0; a.y = h1; b.x = h2; b.y = h3;
    ((__nv_bfloat162*)dh)[2*i]   = a;
    ((__nv_bfloat162*)dh)[2*i+1] = b;
    a.x = l0; a.y = l1; b.x = l2; b.y = l3;
    ((__nv_bfloat162*)dl)[2*i]   = a;
    ((__nv_bfloat162*)dl)[2*i+1] = b;
}

// ---------------- LayerNorm ----------------
template<int BF>
__global__ void __launch_bounds__(256) ln_kernel(const float* __restrict__ x,
                                                 const float* __restrict__ g,
                                                 const float* __restrict__ b,
                                                 float* __restrict__ y,
                                                 __nv_bfloat16* __restrict__ yh,
                                                 __nv_bfloat16* __restrict__ yl) {
    int row = blockIdx.x;
    int t   = threadIdx.x;
    const float4* xr = (const float4*)(x + (size_t)row * HDIM);
    float4 v = xr[t];

    float sum = v.x + v.y + v.z + v.w;
    float sq  = v.x*v.x + v.y*v.y + v.z*v.z + v.w*v.w;
    #pragma unroll
    for (int o = 16; o > 0; o >>= 1) {
        sum += __shfl_down_sync(0xffffffffu, sum, o);
        sq  += __shfl_down_sync(0xffffffffu, sq,  o);
    }
    __shared__ float red[64];
    __shared__ float stats[2];
    int lane = t & 31, wid = t >> 5;
    if (lane == 0) { red[wid] = sum; red[32 + wid] = sq; }
    __syncthreads();
    if (t == 0) {
        float s1 = 0.f, s2 = 0.f;
        #pragma unroll
        for (int i = 0; i < 8; i++) { s1 += red[i]; s2 += red[32 + i]; }
        float mu  = s1 * (1.0f / HDIM);
        float var = s2 * (1.0f / HDIM) - mu * mu;
        stats[0] = mu;
        stats[1] = rsqrtf(var + 1e-5f);
    }
    __syncthreads();
    float mu = stats[0], inv = stats[1];
    float4 gg = ((const float4*)g)[t];
    float4 bb = ((const float4*)b)[t];
    float4 o;
    o.x = (v.x - mu) * inv * gg.x + bb.x;
    o.y = (v.y - mu) * inv * gg.y + bb.y;
    o.z = (v.z - mu) * inv * gg.z + bb.z;
    o.w = (v.w - mu) * inv * gg.w + bb.w;
    if (BF) {
        __nv_bfloat16 h0,h1,h2,h3,l0,l1,l2,l3;
        split_bf16(o.x,h0,l0); split_bf16(o.y,h1,l1);
        split_bf16(o.z,h2,l2); split_bf16(o.w,h3,l3);
        __nv_bfloat162 p0, p1;
        p0.x=h0; p0.y=h1; p1.x=h2; p1.y=h3;
        ((__nv_bfloat162*)(yh + (size_t)row*HDIM + 4*t))[0] = p0;
        ((__nv_bfloat162*)(yh + (size_t)row*HDIM + 4*t))[1] = p1;
        p0.x=l0; p0.y=l1; p1.x=l2; p1.y=l3;
        ((__nv_bfloat162*)(yl + (size_t)row*HDIM + 4*t))[0] = p0;
        ((__nv_bfloat162*)(yl + (size_t)row*HDIM + 4*t))[1] = p1;
    } else {
        ((float4*)(y + (size_t)row * HDIM))[t] = o;
    }
}

// ---------------- RoPE + split; q scaled by (1/8)*log2(e) for exp2-domain softmax ----
__global__ void rope_kernel(const float* __restrict__ qkv, int S) {
    int idx = blockIdx.x * blockDim.x + threadIdx.x;
    if (idx >= S * NHEAD * 32) return;
    int p    = idx & 31;
    int head = (idx >> 5) & (NHEAD - 1);
    int s    = idx >> 9;
    float c  = g_cos[s * 32 + p];
    float sn = g_sin[s * 32 + p];
    size_t src = (size_t)s * (3 * HDIM) + head * HEADD + 2 * p;
    size_t dst = (size_t)s * HDIM + head * HEADD + 2 * p;
    const float QSC = 0.125f * 1.4426950408889634f;
    float a, b, r0, r1;
    __nv_bfloat16 h0,h1,l0,l1;
    __nv_bfloat162 hp, lp;

    a = qkv[src]; b = qkv[src + 1];
    r0 = (a * c - b * sn) * QSC;
    r1 = (a * sn + b * c) * QSC;
    split_bf16(r0, h0, l0); split_bf16(r1, h1, l1);
    hp.x=h0; hp.y=h1; lp.x=l0; lp.y=l1;
    *(__nv_bfloat162*)(g_qhh + dst) = hp;
    *(__nv_bfloat162*)(g_qll + dst) = lp;

    a = qkv[src + HDIM]; b = qkv[src + HDIM + 1];
    r0 = a * c - b * sn;
    r1 = a * sn + b * c;
    split_bf16(r0, h0, l0); split_bf16(r1, h1, l1);
    hp.x=h0; hp.y=h1; lp.x=l0; lp.y=l1;
    *(__nv_bfloat162*)(g_khh + dst) = hp;
    *(__nv_bfloat162*)(g_kll + dst) = lp;

    a = qkv[src + 2*HDIM]; b = qkv[src + 2*HDIM + 1];
    split_bf16(a, h0, l0); split_bf16(b, h1, l1);
    hp.x=h0; hp.y=h1; lp.x=l0; lp.y=l1;
    *(__nv_bfloat162*)(g_vhh + dst) = hp;
    *(__nv_bfloat162*)(g_vll + dst) = lp;
}

// =================== tcgen05 bf16x3 GEMM (sm_103a cubin only) ===================
#define TC_IDESC 0x8400490u
#define TC_NT 256
#define TC_STAGE 98304
#define TC_SMEM (1024 + 2 * TC_STAGE)
#define TC_DESC(addr) ((2ull << 61) | (1ull << 46) | (64ull << 32) | (1ull << 16) \
                       | (((uint64_t)((addr) >> 4)) & 0x3FFF))

// ----- TMA variant; mainloop reordered so mma(i+1) is queued before waiting done(i) ----
template<int EPI>
__global__ void __launch_bounds__(256, 1)
gemm_tc_tma(const __grid_constant__ CUtensorMap tAh, const __grid_constant__ CUtensorMap tAl,
            const __grid_constant__ CUtensorMap tBh, const __grid_constant__ CUtensorMap tBl,
            float* __restrict__ C, __nv_bfloat16* __restrict__ Ch, __nv_bfloat16* __restrict__ Cl,
            const float* __restrict__ bias, const float* __restrict__ res,
            int Nt, int Kt)
{
#if TC_OK
    extern __shared__ char tsm[];
    uint32_t sb  = (uint32_t)__cvta_generic_to_shared(tsm);
    int tid  = threadIdx.x;
    int wid  = tid >> 5;
    int lane = tid & 31;

    int m0 = blockIdx.y * 128;
    int n0 = blockIdx.x * TC_NT;

    uint32_t mf[2] = { sb + 8,  sb + 16 };
    uint32_t md[2] = { sb + 24, sb + 32 };
    uint32_t stg[2] = { sb + 1024, sb + 1024 + TC_STAGE };

    if (wid == 0) {
        tc_alloc(sb, TC_NT);
        tc_relinq();
    }
    if (tid == 0) {
        mbar_init(mf[0], 1); mbar_init(mf[1], 1);
        mbar_init(md[0], 1); mbar_init(md[1], 1);
    }
    __syncthreads();
    uint32_t tmem;
    asm volatile("ld.shared.b32 %0, [%1];" : "=r"(tmem) : "r"(sb));

    int NC = Kt >> 6;

    if (wid == 0) {
        if (elect_one()) {
            mbar_expect_tx(mf[0], TC_STAGE);
            tma2d(stg[0],         &tAh, 0, m0, mf[0]);
            tma2d(stg[0] + 16384, &tAl, 0, m0, mf[0]);
            tma2d(stg[0] + 32768, &tBh, 0, n0, mf[0]);
            tma2d(stg[0] + 65536, &tBl, 0, n0, mf[0]);
            mbar_expect_tx(mf[1], TC_STAGE);
            tma2d(stg[1],         &tAh, 64, m0, mf[1]);
            tma2d(stg[1] + 16384, &tAl, 64, m0, mf[1]);
            tma2d(stg[1] + 32768, &tBh, 64, n0, mf[1]);
            tma2d(stg[1] + 65536, &tBl, 64, n0, mf[1]);
        }
        uint32_t pf[2] = {0, 0}, pd[2] = {0, 0};
        // issue mma(0) up front
        mbar_wait(mf[0], 0); pf[0] = 1;
        if (elect_one()) {
            uint64_t adh = TC_DESC(stg[0]);
            uint64_t adl = TC_DESC(stg[0] + 16384);
            uint64_t bdh = TC_DESC(stg[0] + 32768);
            uint64_t bdl = TC_DESC(stg[0] + 65536);
            #pragma unroll
            for (int ks = 0; ks < 4; ks++) {
                tc_mma(tmem, adh + ks*2, bdh + ks*2, TC_IDESC, ks ? 1u : 0u);
                tc_mma(tmem, adl + ks*2, bdh + ks*2, TC_IDESC, 1u);
                tc_mma(tmem, adh + ks*2, bdl + ks*2, TC_IDESC, 1u);
            }
            tc_commit(md[0]);
        }
        for (int i = 0; i < NC; i++) {
            int s = i & 1, s1 = s ^ 1;
            // queue mma(i+1) first (tensor pipe stays fed while mma(i) runs)
            if (i + 1 < NC) {
                mbar_wait(mf[s1], pf[s1] & 1); pf[s1]++;
                if (elect_one()) {
                    uint64_t adh = TC_DESC(stg[s1]);
                    uint64_t adl = TC_DESC(stg[s1] + 16384);
                    uint64_t bdh = TC_DESC(stg[s1] + 32768);
                    uint64_t bdl = TC_DESC(stg[s1] + 65536);
                    #pragma unroll
                    for (int ks = 0; ks < 4; ks++) {
                        tc_mma(tmem, adh + ks*2, bdh + ks*2, TC_IDESC, 1u);
                        tc_mma(tmem, adl + ks*2, bdh + ks*2, TC_IDESC, 1u);
                        tc_mma(tmem, adh + ks*2, bdl + ks*2, TC_IDESC, 1u);
                    }
                    tc_commit(md[s1]);
                }
            }
            // now retire mma(i) and refill its stage
            mbar_wait(md[s], pd[s] & 1); pd[s]++;
            if (i + 2 < NC) {
                if (elect_one()) {
                    int k0 = (i + 2) << 6;
                    mbar_expect_tx(mf[s], TC_STAGE);
                    tma2d(stg[s],         &tAh, k0, m0, mf[s]);
                    tma2d(stg[s] + 16384, &tAl, k0, m0, mf[s]);
                    tma2d(stg[s] + 32768, &tBh, k0, n0, mf[s]);
                    tma2d(stg[s] + 65536, &tBl, k0, n0, mf[s]);
                }
            }
        }
    }
    __syncthreads();
    tc_fence_after();

    int rowl  = (wid & 3) * 32 + lane;
    int halfc = (wid >> 2) * 128;
    size_t mg = (size_t)(m0 + rowl);
    #pragma unroll
    for (int cc = 0; cc < 4; cc++) {
        int c0 = halfc + cc * 32;
        uint32_t r[32];
        ldtm_x32(r, tmem + c0);
        tc_wait_ld();
        int ng = n0 + c0;
        if (EPI == 2) {
            #pragma unroll
            for (int j = 0; j < 32; j += 2) {
                float v0 = __uint_as_float(r[j])   + bias[ng + j];
                float v1 = __uint_as_float(r[j+1]) + bias[ng + j + 1];
                v0 = 0.5f * v0 * (1.0f + erff(v0 * 0.7071067811865476f));
                v1 = 0.5f * v1 * (1.0f + erff(v1 * 0.7071067811865476f));
                __nv_bfloat16 h0,h1,l0,l1;
                split_bf16(v0,h0,l0); split_bf16(v1,h1,l1);
                __nv_bfloat162 p;
                p.x=h0; p.y=h1; *(__nv_bfloat162*)(Ch + mg*Nt + ng + j) = p;
                p.x=l0; p.y=l1; *(__nv_bfloat162*)(Cl + mg*Nt + ng + j) = p;
            }
        } else {
            #pragma unroll
            for (int j = 0; j < 8; j++) {
                float4 v;
                v.x = __uint_as_float(r[4*j]);
                v.y = __uint_as_float(r[4*j+1]);
                v.z = __uint_as_float(r[4*j+2]);
                v.w = __uint_as_float(r[4*j+3]);
                if (EPI == 3) {
                    float4 bv = *(const float4*)(bias + ng + 4*j);
                    v.x += bv.x; v.y += bv.y; v.z += bv.z; v.w += bv.w;
                }
                if (EPI == 1 || EPI == 3) {
                    float4 rv = *(const float4*)(res + mg*Nt + ng + 4*j);
                    v.x += rv.x; v.y += rv.y; v.z += rv.z; v.w += rv.w;
                }
                *(float4*)(C + mg*Nt + ng + 4*j) = v;
            }
        }
    }

    __syncthreads();
    if (tid == 0) { mbar_inval(mf[0]); mbar_inval(mf[1]); mbar_inval(md[0]); mbar_inval(md[1]); }
    __syncthreads();
    if (wid == 0) tc_dealloc(tmem, TC_NT);
#endif
}

// =================== tcgen05 flash attention (R9 version — best known) ===================
// CTA = (q-tile 128, head), 128 threads (4 warps). S and O accumulate in TMEM.
#define ATC_Q   1024
#define ATC_ST0 (ATC_Q + 32768)
#define ATC_ST1 (ATC_ST0 + 32768)
#define ATC_VT  (ATC_ST1 + 32768)
#define ATC_SMEM (ATC_VT + 16384)
#define ATC_IDESC 0x8100490u   // f16 kind, M=128, N=64

__global__ void __launch_bounds__(128)
attn_tc(const __grid_constant__ CUtensorMap mQh, const __grid_constant__ CUtensorMap mQl,
        const __grid_constant__ CUtensorMap mKh, const __grid_constant__ CUtensorMap mKl,
        const __grid_constant__ CUtensorMap mVh, const __grid_constant__ CUtensorMap mVl,
        __nv_bfloat16* __restrict__ oh, __nv_bfloat16* __restrict__ ol, int S)
{
#if TC_OK
    extern __shared__ char asm_[];
    uint32_t sb = (uint32_t)__cvta_generic_to_shared(asm_);
    int tid  = threadIdx.x;
    int wid  = tid >> 5;
    int lane = tid & 31;
    int head = blockIdx.y;
    int q0   = blockIdx.x * 128;
    int hx   = head * HEADD;

    int segs = 0, sege = S;
    int ng = g_nseg;
    for (int g = 0; g < ng; g++) {
        if (q0 >= g_bounds[g] && q0 < g_bounds[g+1]) {
            segs = g_bounds[g]; sege = g_bounds[g+1]; break;
        }
    }
    int niter = (sege - segs) >> 6;

    uint32_t mf0 = sb + 8, mf1 = sb + 16, mbs = sb + 24, mbo = sb + 32;
    uint32_t stg[2] = { sb + ATC_ST0, sb + ATC_ST1 };
    uint32_t vt = sb + ATC_VT;

    if (wid == 0) { tc_alloc(sb, 256); tc_relinq(); }
    if (tid == 0) {
        mbar_init(mf0, 1); mbar_init(mf1, 1);
        mbar_init(mbs, 1); mbar_init(mbo, 1);
    }
    __syncthreads();
    uint32_t tmem;
    asm volatile("ld.shared.b32 %0, [%1];" : "=r"(tmem) : "r"(sb));
    uint32_t tm_s = tmem, tm_o = tmem + 64, tm_ph = tmem + 128, tm_pl = tmem + 160;
    uint32_t woff = (uint32_t)wid << 21;

    if (tid == 0) {
        mbar_expect_tx(mf0, 32768 + 32768);
        tma2d(sb + ATC_Q,          &mQh, hx, q0, mf0);
        tma2d(sb + ATC_Q + 16384,  &mQl, hx, q0, mf0);
        tma2d(stg[0],              &mKh, hx, segs, mf0);
        tma2d(stg[0] + 8192,       &mKl, hx, segs, mf0);
        tma2d(stg[0] + 16384,      &mVh, hx, segs, mf0);
        tma2d(stg[0] + 24576,      &mVl, hx, segs, mf0);
        if (niter > 1) {
            mbar_expect_tx(mf1, 32768);
            tma2d(stg[1],          &mKh, hx, segs + 64, mf1);
            tma2d(stg[1] + 8192,   &mKl, hx, segs + 64, mf1);
            tma2d(stg[1] + 16384,  &mVh, hx, segs + 64, mf1);
            tma2d(stg[1] + 24576,  &mVl, hx, segs + 64, mf1);
        }
    }

    uint64_t qdh = TC_DESC(sb + ATC_Q);
    uint64_t qdl = TC_DESC(sb + ATC_Q + 16384);
    uint64_t vtdh = TC_DESC(vt);
    uint64_t vtdl = TC_DESC(vt + 8192);

    float mrow = -1e30f, lrow = 0.f;
    uint32_t pf[2] = {0, 0};
    uint32_t ph_s = 0, ph_o = 0;

    for (int i = 0; i < niter; i++) {
        int s = i & 1;
        uint32_t mf = s ? mf1 : mf0;
        mbar_wait(mf, pf[s] & 1); pf[s]++;
        if (i > 0) { mbar_wait(mbo, ph_o & 1); ph_o++; tc_fence_after(); }

        // transpose V (hi & lo) stage -> VT
        {
            uint32_t stV = stg[s] + 16384;
            int r8 = lane & 7;
            #pragma unroll
            for (int g = 0; g < 4; g++) {
                int t = wid * 16 + g * 4 + (lane >> 3);
                int kr = t >> 3, dc = t & 7;
                int srow = kr * 8 + r8;
                uint32_t saddr = stV + srow * 128 + (uint32_t)(((dc ^ (srow & 7))) << 4);
                int drow = dc * 8 + r8;
                uint32_t daddr = vt + drow * 128 + (uint32_t)(((kr ^ (drow & 7))) << 4);
                uint32_t rr[4];
                ldm_x4_t(rr, saddr);
                stm_x4(daddr, rr);
                ldm_x4_t(rr, saddr + 8192);
                stm_x4(daddr + 8192, rr);
            }
        }
        fence_proxy_async_s();
        __syncthreads();

        // QK^T -> S
        if (wid == 0) {
            tc_fence_after();
            if (elect_one()) {
                uint64_t kdh = TC_DESC(stg[s]);
                uint64_t kdl = TC_DESC(stg[s] + 8192);
                #pragma unroll
                for (int ks = 0; ks < 4; ks++) {
                    tc_mma(tm_s, qdh + ks*2, kdh + ks*2, ATC_IDESC, ks ? 1u : 0u);
                    tc_mma(tm_s, qdl + ks*2, kdh + ks*2, ATC_IDESC, 1u);
                    tc_mma(tm_s, qdh + ks*2, kdl + ks*2, ATC_IDESC, 1u);
                }
                tc_commit(mbs);
            }
        }
        mbar_wait(mbs, ph_s & 1); ph_s++;
        tc_fence_after();

        if (i + 2 < niter && tid == 0) {
            int k0 = segs + (i + 2) * 64;
            mbar_expect_tx(mf, 32768);
            tma2d(stg[s],         &mKh, hx, k0, mf);
            tma2d(stg[s] + 8192,  &mKl, hx, k0, mf);
            tma2d(stg[s] + 16384, &mVh, hx, k0, mf);
            tma2d(stg[s] + 24576, &mVl, hx, k0, mf);
        }

        float sv[64];
        ldtm_x32((uint32_t*)sv,      tm_s);
        ldtm_x32((uint32_t*)(sv+32), tm_s + 32);
        tc_wait_ld();

        float rmax = sv[0];
        #pragma unroll
        for (int j = 1; j < 64; j++) rmax = fmaxf(rmax, sv[j]);
        float mnew  = fmaxf(mrow, rmax);
        float alpha = ex2f(mrow - mnew);
        mrow = mnew;
        float sum = 0.f;
        #pragma unroll
        for (int j = 0; j < 64; j++) { sv[j] = ex2f(sv[j] - mnew); sum += sv[j]; }
        lrow = lrow * alpha + sum;

        uint32_t phr[32], plr[32];
        #pragma unroll
        for (int c = 0; c < 32; c++) phr[c] = pack_bf16_hi(sv[2*c], sv[2*c+1], plr[c]);
        sttm_x32(tm_ph + woff, phr);
        sttm_x32(tm_pl + woff, plr);
        tc_wait_st();

        if (i > 0) {
            float ov[64];
            ldtm_x32((uint32_t*)ov,      tm_o);
            ldtm_x32((uint32_t*)(ov+32), tm_o + 32);
            tc_wait_ld();
            #pragma unroll
            for (int j = 0; j < 64; j++) ov[j] *= alpha;
            sttm_x32(tm_o + woff,      (uint32_t*)ov);
            sttm_x32(tm_o + 32 + woff, (uint32_t*)(ov+32));
            tc_wait_st();
        }
        tc_fence_before();
        __syncthreads();

        if (wid == 0) {
            tc_fence_after();
            if (elect_one()) {
                #pragma unroll
                for (int ks = 0; ks < 4; ks++) {
                    tc_mma_ts(tm_o, tm_ph + ks*8, vtdh + ks*2, ATC_IDESC,
                              (i | ks) ? 1u : 0u);
                    tc_mma_ts(tm_o, tm_pl + ks*8, vtdh + ks*2, ATC_IDESC, 1u);
                    tc_mma_ts(tm_o, tm_ph + ks*8, vtdl + ks*2, ATC_IDESC, 1u);
                }
                tc_commit(mbo);
            }
        }
    }

    mbar_wait(mbo, ph_o & 1);
    tc_fence_after();

    float ov[64];
    ldtm_x32((uint32_t*)ov,      tm_o);
    ldtm_x32((uint32_t*)(ov+32), tm_o + 32);
    tc_wait_ld();
    float il = 1.0f / lrow;
    size_t base = (size_t)(q0 + wid * 32 + lane) * HDIM + hx;
    #pragma unroll
    for (int c = 0; c < 32; c++) {
        float v0 = ov[2*c] * il, v1 = ov[2*c+1] * il;
        __nv_bfloat16 h0,h1,l0,l1;
        split_bf16(v0,h0,l0); split_bf16(v1,h1,l1);
        __nv_bfloat162 p;
        p.x=h0; p.y=h1; *(__nv_bfloat162*)(oh + base + 2*c) = p;
        p.x=l0; p.y=l1; *(__nv_bfloat162*)(ol + base + 2*c) = p;
    }

    __syncthreads();
    if (tid == 0) { mbar_inval(mf0); mbar_inval(mf1); mbar_inval(mbs); mbar_inval(mbo); }
    __syncthreads();
    if (wid == 0) tc_dealloc(tmem, 256);
#endif
}

// ---------------- FA2 mma.sync attention (fallback) ----------------
#define AST 72
#define ATILE (64 * AST)
#define ASTAGE (4 * ATILE * 2)
#define ATTN_SMEM_BYTES (2 * ASTAGE)

__global__ void __launch_bounds__(256) attn_kernel(
    const __nv_bfloat16* __restrict__ qh, const __nv_bfloat16* __restrict__ ql,
    const __nv_bfloat16* __restrict__ kh, const __nv_bfloat16* __restrict__ kl,
    const __nv_bfloat16* __restrict__ vh, const __nv_bfloat16* __restrict__ vl,
    __nv_bfloat16* __restrict__ oh, __nv_bfloat16* __restrict__ ol, int S)
{
    extern __shared__ char smraw[];
    uint32_t sb  = (uint32_t)__cvta_generic_to_shared(smraw);

    int head = blockIdx.y;
    int q0   = blockIdx.x * 128;
    int tid  = threadIdx.x;
    int lane = tid & 31;
    int wid  = tid >> 5;
    int grp  = lane >> 2;
    int tig  = lane & 3;

    int segs = 0, sege = S;
    int ng = g_nseg;
    for (int g = 0; g < ng; g++) {
        if (q0 >= g_bounds[g] && q0 < g_bounds[g+1]) {
            segs = g_bounds[g]; sege = g_bounds[g+1]; break;
        }
    }

    int qrow = q0 + wid * 16 + grp;
    uint32_t qfh[4][4], qfl[4][4];
    #pragma unroll
    for (int kc = 0; kc < 4; kc++) {
        #pragma unroll
        for (int i = 0; i < 4; i++) {
            int r = qrow + (i & 1) * 8;
            int c = kc * 16 + (i >> 1) * 8 + 2 * tig;
            size_t off = (size_t)r * HDIM + head * HEADD + c;
            qfh[kc][i] = *(const uint32_t*)(qh + off);
            qfl[kc][i] = *(const uint32_t*)(ql + off);
        }
    }

    float m0 = -1e30f, m1 = -1e30f, l0 = 0.f, l1 = 0.f;
    float oacc[8][4];
    #pragma unroll
    for (int j = 0; j < 8; j++)
        #pragma unroll
        for (int c = 0; c < 4; c++) oacc[j][c] = 0.f;

    int brow = (lane & 7) + ((lane & 16) >> 1), bcol = lane & 8;
    int vrow = lane & 15,  vcol = (lane >> 4) << 3;

    int f0 = tid,        r0_ = f0 >> 3, c80 = (f0 & 7) << 3;
    int f1 = tid + 256,  r1_ = f1 >> 3, c81 = (f1 & 7) << 3;
    uint32_t so0 = (uint32_t)(r0_ * AST + c80) * 2;
    uint32_t so1 = (uint32_t)(r1_ * AST + c81) * 2;

    int niter = (sege - segs) >> 6;

    {
        size_t gs0 = (size_t)(segs + r0_) * HDIM + head * HEADD + c80;
        size_t gs1 = (size_t)(segs + r1_) * HDIM + head * HEADD + c81;
        cp16(sb + so0,             kh + gs0); cp16(sb + so1,             kh + gs1);
        cp16(sb + ATILE*2 + so0,   kl + gs0); cp16(sb + ATILE*2 + so1,   kl + gs1);
        cp16(sb + 2*ATILE*2 + so0, vh + gs0); cp16(sb + 2*ATILE*2 + so1, vh + gs1);
        cp16(sb + 3*ATILE*2 + so0, vl + gs0); cp16(sb + 3*ATILE*2 + so1, vl + gs1);
        asm volatile("cp.async.commit_group;" ::);
    }

    for (int it = 0; it < niter; it++) {
        if (it + 1 < niter) {
            int k0n = segs + (it + 1) * 64;
            uint32_t stb = sb + ((it + 1) & 1) * ASTAGE;
            size_t gs0 = (size_t)(k0n + r0_) * HDIM + head * HEADD + c80;
            size_t gs1 = (size_t)(k0n + r1_) * HDIM + head * HEADD + c81;
            cp16(stb + so0,             kh + gs0); cp16(stb + so1,             kh + gs1);
            cp16(stb + ATILE*2 + so0,   kl + gs0); cp16(stb + ATILE*2 + so1,   kl + gs1);
            cp16(stb + 2*ATILE*2 + so0, vh + gs0); cp16(stb + 2*ATILE*2 + so1, vh + gs1);
            cp16(stb + 3*ATILE*2 + so0, vl + gs0); cp16(stb + 3*ATILE*2 + so1, vl + gs1);
            asm volatile("cp.async.commit_group;" ::);
            asm volatile("cp.async.wait_group 1;" ::);
        } else {
            asm volatile("cp.async.wait_group 0;" ::);
        }
        __syncthreads();

        uint32_t bKh = sb + (it & 1) * ASTAGE;
        uint32_t bKl = bKh + ATILE * 2;
        uint32_t bVh = bKh + 2 * ATILE * 2;
        uint32_t bVl = bKh + 3 * ATILE * 2;

        float sacc[8][4];
        #pragma unroll
        for (int j = 0; j < 8; j++)
            #pragma unroll
            for (int c = 0; c < 4; c++) sacc[j][c] = 0.f;
        #pragma unroll
        for (int kc = 0; kc < 4; kc++) {
            int kk = kc << 4;
            uint32_t bb[8][2];
            #pragma unroll
            for (int jj = 0; jj < 4; jj++) {
                uint32_t rb = ((jj*16 + brow) * AST + kk + bcol) * 2;
                uint32_t tr[4];
                ldm_x4(tr, bKh + rb);
                bb[2*jj][0]=tr[0]; bb[2*jj][1]=tr[1]; bb[2*jj+1][0]=tr[2]; bb[2*jj+1][1]=tr[3];
            }
            #pragma unroll
            for (int j = 0; j < 8; j++) {
                mma_bf16(sacc[j], qfh[kc], bb[j]);
                mma_bf16(sacc[j], qfl[kc], bb[j]);
            }
            #pragma unroll
            for (int jj = 0; jj < 4; jj++) {
                uint32_t rb = ((jj*16 + brow) * AST + kk + bcol) * 2;
                uint32_t tr[4];
                ldm_x4(tr, bKl + rb);
                bb[2*jj][0]=tr[0]; bb[2*jj][1]=tr[1]; bb[2*jj+1][0]=tr[2]; bb[2*jj+1][1]=tr[3];
            }
            #pragma unroll
            for (int j = 0; j < 8; j++)
                mma_bf16(sacc[j], qfh[kc], bb[j]);
        }

        float r0 = -1e30f, r1 = -1e30f;
        #pragma unroll
        for (int j = 0; j < 8; j++) {
            r0 = fmaxf(r0, fmaxf(sacc[j][0], sacc[j][1]));
            r1 = fmaxf(r1, fmaxf(sacc[j][2], sacc[j][3]));
        }
        r0 = fmaxf(r0, __shfl_xor_sync(0xffffffffu, r0, 1));
        r0 = fmaxf(r0, __shfl_xor_sync(0xffffffffu, r0, 2));
        r1 = fmaxf(r1, __shfl_xor_sync(0xffffffffu, r1, 1));
        r1 = fmaxf(r1, __shfl_xor_sync(0xffffffffu, r1, 2));
        float mn0 = fmaxf(m0, r0), mn1 = fmaxf(m1, r1);
        float al0 = ex2f(m0 - mn0), al1 = ex2f(m1 - mn1);
        float sum0 = 0.f, sum1 = 0.f;
        #pragma unroll
        for (int j = 0; j < 8; j++) {
            sacc[j][0] = ex2f(sacc[j][0] - mn0); sum0 += sacc[j][0];
            sacc[j][1] = ex2f(sacc[j][1] - mn0); sum0 += sacc[j][1];
            sacc[j][2] = ex2f(sacc[j][2] - mn1); sum1 += sacc[j][2];
            sacc[j][3] = ex2f(sacc[j][3] - mn1); sum1 += sacc[j][3];
        }
        sum0 += __shfl_xor_sync(0xffffffffu, sum0, 1);
        sum0 += __shfl_xor_sync(0xffffffffu, sum0, 2);
        sum1 += __shfl_xor_sync(0xffffffffu, sum1, 1);
        sum1 += __shfl_xor_sync(0xffffffffu, sum1, 2);
        l0 = l0 * al0 + sum0;
        l1 = l1 * al1 + sum1;
        m0 = mn0; m1 = mn1;
        #pragma unroll
        for (int j = 0; j < 8; j++) {
            oacc[j][0] *= al0; oacc[j][1] *= al0;
            oacc[j][2] *= al1; oacc[j][3] *= al1;
        }

        #pragma unroll
        for (int kc = 0; kc < 4; kc++) {
            uint32_t pfh[4], pfl[4];
            pfh[0] = pack_bf16_hi(sacc[2*kc][0],   sacc[2*kc][1],   pfl[0]);
            pfh[1] = pack_bf16_hi(sacc[2*kc][2],   sacc[2*kc][3],   pfl[1]);
            pfh[2] = pack_bf16_hi(sacc[2*kc+1][0], sacc[2*kc+1][1], pfl[2]);
            pfh[3] = pack_bf16_hi(sacc[2*kc+1][2], sacc[2*kc+1][3], pfl[3]);
            uint32_t bb[8][2];
            #pragma unroll
            for (int jn = 0; jn < 4; jn++) {
                uint32_t rb = ((kc*16 + vrow) * AST + jn*16 + vcol) * 2;
                uint32_t tr[4];
                ldm_x4_t(tr, bVh + rb);
                bb[2*jn][0]=tr[0]; bb[2*jn][1]=tr[1]; bb[2*jn+1][0]=tr[2]; bb[2*jn+1][1]=tr[3];
            }
            #pragma unroll
            for (int j = 0; j < 8; j++) {
                mma_bf16(oacc[j], pfh, bb[j]);
                mma_bf16(oacc[j], pfl, bb[j]);
            }
            #pragma unroll
            for (int jn = 0; jn < 4; jn++) {
                uint32_t rb = ((kc*16 + vrow) * AST + jn*16 + vcol) * 2;
                uint32_t tr[4];
                ldm_x4_t(tr, bVl + rb);
                bb[2*jn][0]=tr[0]; bb[2*jn][1]=tr[1]; bb[2*jn+1][0]=tr[2]; bb[2*jn+1][1]=tr[3];
            }
            #pragma unroll
            for (int j = 0; j < 8; j++)
                mma_bf16(oacc[j], pfh, bb[j]);
        }
        __syncthreads();
    }

    float il0 = 1.0f / l0, il1 = 1.0f / l1;
    #pragma unroll
    for (int j = 0; j < 8; j++) {
        int d = j * 8 + 2 * tig;
        float v0 = oacc[j][0] * il0, v1 = oacc[j][1] * il0;
        float v2 = oacc[j][2] * il1, v3 = oacc[j][3] * il1;
        __nv_bfloat16 h0,h1,h2,h3,lo0,lo1,lo2,lo3;
        split_bf16(v0,h0,lo0); split_bf16(v1,h1,lo1);
        split_bf16(v2,h2,lo2); split_bf16(v3,h3,lo3);
        size_t p0 = (size_t)qrow * HDIM + head * HEADD + d;
        size_t p1 = (size_t)(qrow + 8) * HDIM + head * HEADD + d;
        __nv_bfloat162 p;
        p.x=h0;  p.y=h1;  *(__nv_bfloat162*)(oh + p0) = p;
        p.x=h2;  p.y=h3;  *(__nv_bfloat162*)(oh + p1) = p;
        p.x=lo0; p.y=lo1; *(__nv_bfloat162*)(ol + p0) = p;
        p.x=lo2; p.y=lo3; *(__nv_bfloat162*)(ol + p1) = p;
    }
}

// ---------------- launch ----------------
typedef CUresult (*PFN_tmap_enc)(
    CUtensorMap*, CUtensorMapDataType, cuuint32_t, void*,
    const cuuint64_t*, const cuuint64_t*, const cuuint32_t*, const cuuint32_t*,
    CUtensorMapInterleave, CUtensorMapSwizzle, CUtensorMapL2promotion, CUtensorMapFloatOOBfill);

static bool make_map2d(PFN_tmap_enc fn, CUtensorMap* m, void* base,
                       uint64_t d0, uint64_t d1, uint32_t b0, uint32_t b1) {
    cuuint64_t dims[2]    = {d0, d1};
    cuuint64_t strides[1] = {d0 * 2};
    cuuint32_t box[2]     = {b0, b1};
    cuuint32_t es[2]      = {1, 1};
    return fn(m, CU_TENSOR_MAP_DATA_TYPE_BFLOAT16, 2, base, dims, strides, box, es,
              CU_TENSOR_MAP_INTERLEAVE_NONE, CU_TENSOR_MAP_SWIZZLE_128B,
              CU_TENSOR_MAP_L2_PROMOTION_L2_128B,
              CU_TENSOR_MAP_FLOAT_OOB_FILL_NONE) == CUDA_SUCCESS;
}

extern "C" void kernel_launch(void* const* d_in, const int* in_sizes, int n_in,
                              void* d_out, int out_size) {
    const float* hidden = (const float*)d_in[0];
    const int*   gthw   = (const int*)  d_in[1];
    const float* ln0_g  = (const float*)d_in[2];
    const float* ln0_b  = (const float*)d_in[3];
    const float* wqkv   = (const float*)d_in[4];
    const float* wo     = (const float*)d_in[5];
    const float* ln1_g  = (const float*)d_in[6];
    const float* ln1_b  = (const float*)d_in[7];
    const float* fc0_w  = (const float*)d_in[8];
    const float* fc0_b  = (const float*)d_in[9];
    const float* fc1_w  = (const float*)d_in[10];
    const float* fc1_b  = (const float*)d_in[11];
    const float* fln_g  = (const float*)d_in[12];
    const float* fln_b  = (const float*)d_in[13];

    int S      = in_sizes[0] / HDIM;
    int ngrids = in_sizes[1] / 3;

    float *xp, *qkvp;
    __nv_bfloat16 *hh, *hl, *ohp, *olp, *qhh, *qll, *khh, *kll, *vhh, *vll, *mh, *ml, *wh, *wl;
    cudaGetSymbolAddress((void**)&xp,   g_x);
    cudaGetSymbolAddress((void**)&qkvp, g_qkv);
    cudaGetSymbolAddress((void**)&hh,   g_hh);
    cudaGetSymbolAddress((void**)&hl,   g_hl);
    cudaGetSymbolAddress((void**)&ohp,  g_oh);
    cudaGetSymbolAddress((void**)&olp,  g_ol);
    cudaGetSymbolAddress((void**)&qhh,  g_qhh);
    cudaGetSymbolAddress((void**)&qll,  g_qll);
    cudaGetSymbolAddress((void**)&khh,  g_khh);
    cudaGetSymbolAddress((void**)&kll,  g_kll);
    cudaGetSymbolAddress((void**)&vhh,  g_vhh);
    cudaGetSymbolAddress((void**)&vll,  g_vll);
    cudaGetSymbolAddress((void**)&mh,   g_mh);
    cudaGetSymbolAddress((void**)&ml,   g_ml);
    cudaGetSymbolAddress((void**)&wh,   g_wh);
    cudaGetSymbolAddress((void**)&wl,   g_wl);

    cudaFuncAttributes pa;
    bool use_tc = false;
    if (cudaFuncGetAttributes(&pa, probe_kernel) == cudaSuccess)
        use_tc = (pa.sharedSizeBytes < 64);

    PFN_tmap_enc enc = nullptr;
    {
        void* fp = nullptr;
        cudaDriverEntryPointQueryResult qr;
        if (cudaGetDriverEntryPoint("cuTensorMapEncodeTiled", &fp,
                                    cudaEnableDefault, &qr) == cudaSuccess &&
            qr == cudaDriverEntryPointSuccess)
            enc = (PFN_tmap_enc)fp;
    }
    bool use_tma = use_tc && (enc != nullptr);

    cudaFuncSetAttribute(attn_kernel, cudaFuncAttributeMaxDynamicSharedMemorySize, ATTN_SMEM_BYTES);
    if (use_tma) {
        cudaFuncSetAttribute(gemm_tc_tma<0>, cudaFuncAttributeMaxDynamicSharedMemorySize, TC_SMEM);
        cudaFuncSetAttribute(gemm_tc_tma<1>, cudaFuncAttributeMaxDynamicSharedMemorySize, TC_SMEM);
        cudaFuncSetAttribute(gemm_tc_tma<2>, cudaFuncAttributeMaxDynamicSharedMemorySize, TC_SMEM);
        cudaFuncSetAttribute(gemm_tc_tma<3>, cudaFuncAttributeMaxDynamicSharedMemorySize, TC_SMEM);
        cudaFuncSetAttribute(attn_tc, cudaFuncAttributeMaxDynamicSharedMemorySize, ATC_SMEM);
    }

    const size_t SZ_QKV = (size_t)2 * 3 * HDIM * HDIM;
    const size_t SZ_WO  = (size_t)2 * HDIM * HDIM;
    const size_t SZ_FC0 = (size_t)2 * MDIM * HDIM;
    const size_t OFF_QKV = 0;
    const size_t OFF_WO  = OFF_QKV + SZ_QKV;
    const size_t OFF_FC0 = OFF_WO + SZ_WO;
    const size_t OFF_FC1 = OFF_FC0 + SZ_FC0;

    CUtensorMap mQh, mQl, mKh, mKl, mVh, mVl;
    bool attn_maps_ok = false;
    if (use_tma) {
        attn_maps_ok = make_map2d(enc, &mQh, qhh, HDIM, (uint64_t)S, 64, 128)
                    && make_map2d(enc, &mQl, qll, HDIM, (uint64_t)S, 64, 128)
                    && make_map2d(enc, &mKh, khh, HDIM, (uint64_t)S, 64, 64)
                    && make_map2d(enc, &mKl, kll, HDIM, (uint64_t)S, 64, 64)
                    && make_map2d(enc, &mVh, vhh, HDIM, (uint64_t)S, 64, 64)
                    && make_map2d(enc, &mVl, vll, HDIM, (uint64_t)S, 64, 64);
    }

    auto launch_gemm = [&](int epi, __nv_bfloat16* Ah, __nv_bfloat16* Al,
                           __nv_bfloat16* Bh, __nv_bfloat16* Bl,
                           float* C, __nv_bfloat16* Ch, __nv_bfloat16* Cl,
                           const float* bias, const float* res, int Nt, int Kt) {
        CUtensorMap tAh, tAl, tBh, tBl;
        bool ok = use_tma
               && make_map2d(enc, &tAh, Ah, (uint64_t)Kt, (uint64_t)S,  64, 128)
               && make_map2d(enc, &tAl, Al, (uint64_t)Kt, (uint64_t)S,  64, 128)
               && make_map2d(enc, &tBh, Bh, (uint64_t)Kt, (uint64_t)Nt, 64, 256)
               && make_map2d(enc, &tBl, Bl, (uint64_t)Kt, (uint64_t)Nt, 64, 256);
        dim3 grid(Nt / TC_NT, S / 128);
        if (ok) {
            switch (epi) {
            case 0: gemm_tc_tma<0><<<grid, 256, TC_SMEM>>>(tAh,tAl,tBh,tBl,C,Ch,Cl,bias,res,Nt,Kt); return;
            case 1: gemm_tc_tma<1><<<grid, 256, TC_SMEM>>>(tAh,tAl,tBh,tBl,C,Ch,Cl,bias,res,Nt,Kt); return;
            case 2: gemm_tc_tma<2><<<grid, 256, TC_SMEM>>>(tAh,tAl,tBh,tBl,C,Ch,Cl,bias,res,Nt,Kt); return;
            default: gemm_tc_tma<3><<<grid, 256, TC_SMEM>>>(tAh,tAl,tBh,tBl,C,Ch,Cl,bias,res,Nt,Kt); return;
            }
        }
    };

    {
        int n1 = (int)(SZ_QKV / 4), n2 = (int)(SZ_WO / 4);
        conv2_kernel<<<(n1 + n2 + 255) / 256, 256>>>(
            wqkv, wh + OFF_QKV, wl + OFF_QKV, n1,
            wo,   wh + OFF_WO,  wl + OFF_WO,  n2);
        int n3 = (int)(SZ_FC0 / 4);
        conv2_kernel<<<(2 * n3 + 255) / 256, 256>>>(
            fc0_w, wh + OFF_FC0, wl + OFF_FC0, n3,
            fc1_w, wh + OFF_FC1, wl + OFF_FC1, n3);
    }

    const float* xsrc = hidden;
    for (int l = 0; l < 2; l++) {
        size_t wq  = OFF_QKV + (size_t)l * 3 * HDIM * HDIM;
        size_t w05 = OFF_WO  + (size_t)l * HDIM * HDIM;
        size_t w0  = OFF_FC0 + (size_t)l * MDIM * HDIM;
        size_t w1  = OFF_FC1 + (size_t)l * HDIM * MDIM;

        ln_kernel<1><<<S, 256>>>(xsrc, ln0_g + l * HDIM, ln0_b + l * HDIM, nullptr, hh, hl);
        launch_gemm(0, hh, hl, wh + wq, wl + wq, qkvp, nullptr, nullptr, nullptr, nullptr,
                    3 * HDIM, HDIM);
        if (l == 0) {
            setup_kernel<<<1, 32>>>(gthw, ngrids);
            cossin_kernel<<<(S * 32 + 255) / 256, 256>>>(gthw, ngrids, S);
        }
        rope_kernel<<<(S * NHEAD * 32 + 255) / 256, 256>>>(qkvp, S);
        if (attn_maps_ok) {
            attn_tc<<<dim3(S / 128, NHEAD), 128, ATC_SMEM>>>(
                mQh, mQl, mKh, mKl, mVh, mVl, ohp, olp, S);
        } else {
            attn_kernel<<<dim3(S / 128, NHEAD), 256, ATTN_SMEM_BYTES>>>(
                qhh, qll, khh, kll, vhh, vll, ohp, olp, S);
        }
        launch_gemm(1, ohp, olp, wh + w05, wl + w05, xp, nullptr, nullptr, nullptr, xsrc,
                    HDIM, HDIM);
        ln_kernel<1><<<S, 256>>>(xp, ln1_g + l * HDIM, ln1_b + l * HDIM, nullptr, hh, hl);
        launch_gemm(2, hh, hl, wh + w0, wl + w0, nullptr, mh, ml, fc0_b + l * MDIM, nullptr,
                    MDIM, HDIM);
        launch_gemm(3, mh, ml, wh + w1, wl + w1, xp, nullptr, nullptr, fc1_b + l * HDIM, xp,
                    HDIM, MDIM);
        xsrc = xp;
    }
    ln_kernel<0><<<S, 256>>>(xp, fln_g, fln_b, (float*)d_out, nullptr, nullptr);
}

// round 12
// speedup vs baseline: 1.2660x; 1.2660x over previous
#include <cuda_runtime.h>
#include <cuda.h>
#include <cuda_bf16.h>
#include <math.h>
#include <stdint.h>

#define SEQ   3072
#define HDIM  1024
#define NHEAD 16
#define HEADD 64
#define MDIM  4096

// ---------------- scratch (static device globals; no allocation) ----------------
__device__ float g_x   [(size_t)SEQ * HDIM];
__device__ float g_qkv [(size_t)SEQ * 3 * HDIM];
__device__ __nv_bfloat16 g_hh[(size_t)SEQ * HDIM], g_hl[(size_t)SEQ * HDIM];
__device__ __nv_bfloat16 g_oh[(size_t)SEQ * HDIM], g_ol[(size_t)SEQ * HDIM];
__device__ __nv_bfloat16 g_qhh[(size_t)SEQ * HDIM], g_qll[(size_t)SEQ * HDIM];
__device__ __nv_bfloat16 g_khh[(size_t)SEQ * HDIM], g_kll[(size_t)SEQ * HDIM];
__device__ __nv_bfloat16 g_vhh[(size_t)SEQ * HDIM], g_vll[(size_t)SEQ * HDIM];
__device__ __nv_bfloat16 g_mh[(size_t)SEQ * MDIM], g_ml[(size_t)SEQ * MDIM];
#define WTOT 25165824
__device__ __nv_bfloat16 g_wh[WTOT], g_wl[WTOT];
__device__ float g_cos [(size_t)SEQ * 32];
__device__ float g_sin [(size_t)SEQ * 32];
__device__ int   g_bounds[17];
__device__ int   g_nseg;

// ---------------- generic helpers ----------------
__device__ __forceinline__ void mma_bf16(float* c, const uint32_t* a, const uint32_t* b) {
    asm volatile(
        "mma.sync.aligned.m16n8k16.row.col.f32.bf16.bf16.f32 "
        "{%0,%1,%2,%3}, {%4,%5,%6,%7}, {%8,%9}, {%0,%1,%2,%3};"
        : "+f"(c[0]), "+f"(c[1]), "+f"(c[2]), "+f"(c[3])
        : "r"(a[0]), "r"(a[1]), "r"(a[2]), "r"(a[3]), "r"(b[0]), "r"(b[1]));
}
__device__ __forceinline__ void ldm_x4(uint32_t* r, uint32_t addr) {
    asm volatile("ldmatrix.sync.aligned.m8n8.x4.shared.b16 {%0,%1,%2,%3}, [%4];"
        : "=r"(r[0]), "=r"(r[1]), "=r"(r[2]), "=r"(r[3]) : "r"(addr));
}
__device__ __forceinline__ void ldm_x4_t(uint32_t* r, uint32_t addr) {
    asm volatile("ldmatrix.sync.aligned.m8n8.x4.trans.shared.b16 {%0,%1,%2,%3}, [%4];"
        : "=r"(r[0]), "=r"(r[1]), "=r"(r[2]), "=r"(r[3]) : "r"(addr));
}
__device__ __forceinline__ void stm_x4(uint32_t addr, const uint32_t* r) {
    asm volatile("stmatrix.sync.aligned.m8n8.x4.shared.b16 [%0], {%1,%2,%3,%4};"
        :: "r"(addr), "r"(r[0]), "r"(r[1]), "r"(r[2]), "r"(r[3]) : "memory");
}
__device__ __forceinline__ void cp16(uint32_t smem_addr, const void* gptr) {
    asm volatile("cp.async.cg.shared.global [%0], [%1], 16;" :: "r"(smem_addr), "l"(gptr));
}
__device__ __forceinline__ void split_bf16(float v, __nv_bfloat16& h, __nv_bfloat16& l) {
    h = __float2bfloat16(v);
    l = __float2bfloat16(v - __bfloat162float(h));
}
__device__ __forceinline__ float ex2f(float x) {
    float r;
    asm("ex2.approx.ftz.f32 %0, %1;" : "=f"(r) : "f"(x));
    return r;
}
__device__ __forceinline__ uint32_t pack_bf16_hi(float a, float b, uint32_t& lo) {
    __nv_bfloat16 h0, l0, h1, l1;
    split_bf16(a, h0, l0);
    split_bf16(b, h1, l1);
    __nv_bfloat162 ph, pl;
    ph.x = h0; ph.y = h1;
    pl.x = l0; pl.y = l1;
    lo = *(uint32_t*)&pl;
    return *(uint32_t*)&ph;
}
__device__ __forceinline__ uint32_t elect_one() {
    uint32_t pred;
    asm volatile("{\n\t.reg .pred p;\n\telect.sync _|p, 0xFFFFFFFF;\n\tselp.b32 %0, 1, 0, p;\n\t}"
        : "=r"(pred));
    return pred;
}
__device__ __forceinline__ void mbar_init(uint32_t addr, uint32_t cnt) {
    asm volatile("mbarrier.init.shared.b64 [%0], %1;" :: "r"(addr), "r"(cnt) : "memory");
}
__device__ __forceinline__ void mbar_inval(uint32_t addr) {
    asm volatile("mbarrier.inval.shared.b64 [%0];" :: "r"(addr) : "memory");
}
__device__ __forceinline__ void mbar_wait(uint32_t addr, uint32_t parity) {
    asm volatile(
        "{\n\t.reg .pred P;\n\t"
        "W%=:\n\t"
        "mbarrier.try_wait.parity.acquire.cta.shared::cta.b64 P, [%0], %1, 0x989680;\n\t"
        "@!P bra W%=;\n\t}"
        :: "r"(addr), "r"(parity) : "memory");
}
__device__ __forceinline__ void mbar_expect_tx(uint32_t addr, uint32_t bytes) {
    asm volatile("mbarrier.arrive.expect_tx.shared.b64 _, [%0], %1;"
        :: "r"(addr), "r"(bytes) : "memory");
}
__device__ __forceinline__ void fence_proxy_async_s() {
    asm volatile("fence.proxy.async.shared::cta;" ::: "memory");
}
__device__ __forceinline__ void tma2d(uint32_t dst, const CUtensorMap* m, int x, int y, uint32_t mbar) {
    asm volatile(
        "cp.async.bulk.tensor.2d.shared::cta.global.tile.mbarrier::complete_tx::bytes "
        "[%0], [%1, {%2, %3}], [%4];"
        :: "r"(dst), "l"(m), "r"(x), "r"(y), "r"(mbar) : "memory");
}

// ---------------- tcgen05 helpers (bodies exist only in sm_103a pass) ----------------
#if defined(__CUDA_ARCH__) && defined(__CUDA_ARCH_FEAT_SM103_ALL)
#define TC_OK 1
#else
#define TC_OK 0
#endif

__device__ __forceinline__ void tc_mma(uint32_t d, uint64_t ad, uint64_t bd, uint32_t idesc, uint32_t en) {
#if TC_OK
    asm volatile(
        "{\n\t.reg .pred p;\n\t"
        "setp.ne.u32 p, %5, 0;\n\t"
        "tcgen05.mma.cta_group::1.kind::f16 [%0], %1, %2, %3, {%4, %4, %4, %4}, p;\n\t}"
        :: "r"(d), "l"(ad), "l"(bd), "r"(idesc), "r"(0u), "r"(en) : "memory");
#endif
}
__device__ __forceinline__ void tc_mma_ts(uint32_t d, uint32_t a_tmem, uint64_t bd, uint32_t idesc, uint32_t en) {
#if TC_OK
    asm volatile(
        "{\n\t.reg .pred p;\n\t"
        "setp.ne.u32 p, %5, 0;\n\t"
        "tcgen05.mma.cta_group::1.kind::f16 [%0], [%1], %2, %3, {%4, %4, %4, %4}, p;\n\t}"
        :: "r"(d), "r"(a_tmem), "l"(bd), "r"(idesc), "r"(0u), "r"(en) : "memory");
#endif
}
__device__ __forceinline__ void tc_commit(uint32_t mbar) {
#if TC_OK
    asm volatile(
        "tcgen05.commit.cta_group::1.mbarrier::arrive::one.shared::cluster.b64 [%0];"
        :: "r"(mbar) : "memory");
#endif
}
__device__ __forceinline__ void tc_alloc(uint32_t dst_smem, uint32_t ncols) {
#if TC_OK
    asm volatile("tcgen05.alloc.cta_group::1.sync.aligned.shared::cta.b32 [%0], %1;"
        :: "r"(dst_smem), "r"(ncols) : "memory");
#endif
}
__device__ __forceinline__ void tc_dealloc(uint32_t tmem, uint32_t ncols) {
#if TC_OK
    asm volatile("tcgen05.dealloc.cta_group::1.sync.aligned.b32 %0, %1;" :: "r"(tmem), "r"(ncols));
#endif
}
__device__ __forceinline__ void tc_relinq() {
#if TC_OK
    asm volatile("tcgen05.relinquish_alloc_permit.cta_group::1.sync.aligned;");
#endif
}
__device__ __forceinline__ void ldtm_x32(uint32_t* r, uint32_t tmem) {
#if TC_OK
    asm volatile(
        "tcgen05.ld.sync.aligned.32x32b.x32.b32 "
        "{%0, %1, %2, %3, %4, %5, %6, %7, "
        " %8, %9, %10, %11, %12, %13, %14, %15, "
        " %16, %17, %18, %19, %20, %21, %22, %23, "
        " %24, %25, %26, %27, %28, %29, %30, %31}, [%32];"
        : "=r"(r[0]),  "=r"(r[1]),  "=r"(r[2]),  "=r"(r[3]),
          "=r"(r[4]),  "=r"(r[5]),  "=r"(r[6]),  "=r"(r[7]),
          "=r"(r[8]),  "=r"(r[9]),  "=r"(r[10]), "=r"(r[11]),
          "=r"(r[12]), "=r"(r[13]), "=r"(r[14]), "=r"(r[15]),
          "=r"(r[16]), "=r"(r[17]), "=r"(r[18]), "=r"(r[19]),
          "=r"(r[20]), "=r"(r[21]), "=r"(r[22]), "=r"(r[23]),
          "=r"(r[24]), "=r"(r[25]), "=r"(r[26]), "=r"(r[27]),
          "=r"(r[28]), "=r"(r[29]), "=r"(r[30]), "=r"(r[31])
        : "r"(tmem));
#endif
}
__device__ __forceinline__ void sttm_x32(uint32_t tmem, const uint32_t* r) {
#if TC_OK
    asm volatile(
        "tcgen05.st.sync.aligned.32x32b.x32.b32 [%0], "
        "{%1, %2, %3, %4, %5, %6, %7, %8, "
        " %9, %10, %11, %12, %13, %14, %15, %16, "
        " %17, %18, %19, %20, %21, %22, %23, %24, "
        " %25, %26, %27, %28, %29, %30, %31, %32};"
        :: "r"(tmem),
           "r"(r[0]),  "r"(r[1]),  "r"(r[2]),  "r"(r[3]),
           "r"(r[4]),  "r"(r[5]),  "r"(r[6]),  "r"(r[7]),
           "r"(r[8]),  "r"(r[9]),  "r"(r[10]), "r"(r[11]),
           "r"(r[12]), "r"(r[13]), "r"(r[14]), "r"(r[15]),
           "r"(r[16]), "r"(r[17]), "r"(r[18]), "r"(r[19]),
           "r"(r[20]), "r"(r[21]), "r"(r[22]), "r"(r[23]),
           "r"(r[24]), "r"(r[25]), "r"(r[26]), "r"(r[27]),
           "r"(r[28]), "r"(r[29]), "r"(r[30]), "r"(r[31])
        : "memory");
#endif
}
__device__ __forceinline__ void tc_wait_ld() {
#if TC_OK
    asm volatile("tcgen05.wait::ld.sync.aligned;" ::: "memory");
#endif
}
__device__ __forceinline__ void tc_wait_st() {
#if TC_OK
    asm volatile("tcgen05.wait::st.sync.aligned;" ::: "memory");
#endif
}
__device__ __forceinline__ void tc_fence_after() {
#if TC_OK
    asm volatile("tcgen05.fence::after_thread_sync;" ::: "memory");
#endif
}
__device__ __forceinline__ void tc_fence_before() {
#if TC_OK
    asm volatile("tcgen05.fence::before_thread_sync;" ::: "memory");
#endif
}

// ---------------- probe: static smem marker present only when tcgen05 NOT available ----
__global__ void probe_kernel(int* out) {
#if !(defined(__CUDA_ARCH__) && defined(__CUDA_ARCH_FEAT_SM103_ALL))
    __shared__ int marker[64];
    marker[threadIdx.x & 63] = (int)threadIdx.x;
    __syncthreads();
    if (out) *out = marker[0];
#endif
}

// ---------------- setup: segment boundaries from grid_thws ----------------
__global__ void setup_kernel(const int* __restrict__ grid_thws, int ngrids) {
    if (threadIdx.x == 0 && blockIdx.x == 0) {
        int acc = 0;
        g_bounds[0] = 0;
        for (int g = 0; g < ngrids; g++) {
            acc += grid_thws[3*g] * grid_thws[3*g+1] * grid_thws[3*g+2];
            g_bounds[g+1] = acc;
        }
        g_nseg = ngrids;
    }
}

// ---------------- rope tables ----------------
__global__ void cossin_kernel(const int* __restrict__ grid_thws, int ngrids, int S) {
    int idx = blockIdx.x * blockDim.x + threadIdx.x;
    if (idx >= S * 32) return;
    int s = idx >> 5;
    int p = idx & 31;
    int start = 0, t = 1, h = 1, w = 1, local = 0;
    for (int g = 0; g < ngrids; g++) {
        t = grid_thws[3*g]; h = grid_thws[3*g+1]; w = grid_thws[3*g+2];
        int len = t * h * w;
        if (s < start + len) { local = s - start; break; }
        start += len;
    }
    int hw  = h * w;
    int rem = local % hw;
    int ys  = rem / w;
    int xs  = rem % w;
    int f   = p >> 1;
    double freq = pow(10000.0, -(double)(4 * f) / 64.0);
    double pos  = (p & 1) ? (double)ys : (double)xs;
    double ang  = pos * freq;
    g_cos[idx] = (float)cos(ang);
    g_sin[idx] = (float)sin(ang);
}

// ---------------- weight conversion fp32 -> bf16 hi/lo (2 sources per launch) ---
__global__ void conv2_kernel(const float* __restrict__ s1, __nv_bfloat16* __restrict__ dh1,
                             __nv_bfloat16* __restrict__ dl1, int n1,
                             const float* __restrict__ s2, __nv_bfloat16* __restrict__ dh2,
                             __nv_bfloat16* __restrict__ dl2, int n2) {
    int i = blockIdx.x * 256 + threadIdx.x;
    const float* s;
    __nv_bfloat16 *dh, *dl;
    if (i < n1) { s = s1; dh = dh1; dl = dl1; }
    else {
        i -= n1;
        if (i >= n2) return;
        s = s2; dh = dh2; dl = dl2;
    }
    float4 v = ((const float4*)s)[i];
    __nv_bfloat16 h0, h1, h2, h3, l0, l1, l2, l3;
    split_bf16(v.x, h0, l0); split_bf16(v.y, h1, l1);
    split_bf16(v.z, h2, l2); split_bf16(v.w, h3, l3);
    __nv_bfloat162 a, b;
    a.x = h0; a.y = h1; b.x = h2; b.y = h3;
    ((__nv_bfloat162*)dh)[2*i]   = a;
    ((__nv_bfloat162*)dh)[2*i+1] = b;
    a.x = l0; a.y = l1; b.x = l2; b.y = l3;
    ((__nv_bfloat162*)dl)[2*i]   = a;
    ((__nv_bfloat162*)dl)[2*i+1] = b;
}

// ---------------- LayerNorm ----------------
template<int BF>
__global__ void __launch_bounds__(256) ln_kernel(const float* __restrict__ x,
                                                 const float* __restrict__ g,
                                                 const float* __restrict__ b,
                                                 float* __restrict__ y,
                                                 __nv_bfloat16* __restrict__ yh,
                                                 __nv_bfloat16* __restrict__ yl) {
    int row = blockIdx.x;
    int t   = threadIdx.x;
    const float4* xr = (const float4*)(x + (size_t)row * HDIM);
    float4 v = xr[t];

    float sum = v.x + v.y + v.z + v.w;
    float sq  = v.x*v.x + v.y*v.y + v.z*v.z + v.w*v.w;
    #pragma unroll
    for (int o = 16; o > 0; o >>= 1) {
        sum += __shfl_down_sync(0xffffffffu, sum, o);
        sq  += __shfl_down_sync(0xffffffffu, sq,  o);
    }
    __shared__ float red[64];
    __shared__ float stats[2];
    int lane = t & 31, wid = t >> 5;
    if (lane == 0) { red[wid] = sum; red[32 + wid] = sq; }
    __syncthreads();
    if (t == 0) {
        float s1 = 0.f, s2 = 0.f;
        #pragma unroll
        for (int i = 0; i < 8; i++) { s1 += red[i]; s2 += red[32 + i]; }
        float mu  = s1 * (1.0f / HDIM);
        float var = s2 * (1.0f / HDIM) - mu * mu;
        stats[0] = mu;
        stats[1] = rsqrtf(var + 1e-5f);
    }
    __syncthreads();
    float mu = stats[0], inv = stats[1];
    float4 gg = ((const float4*)g)[t];
    float4 bb = ((const float4*)b)[t];
    float4 o;
    o.x = (v.x - mu) * inv * gg.x + bb.x;
    o.y = (v.y - mu) * inv * gg.y + bb.y;
    o.z = (v.z - mu) * inv * gg.z + bb.z;
    o.w = (v.w - mu) * inv * gg.w + bb.w;
    if (BF) {
        __nv_bfloat16 h0,h1,h2,h3,l0,l1,l2,l3;
        split_bf16(o.x,h0,l0); split_bf16(o.y,h1,l1);
        split_bf16(o.z,h2,l2); split_bf16(o.w,h3,l3);
        __nv_bfloat162 p0, p1;
        p0.x=h0; p0.y=h1; p1.x=h2; p1.y=h3;
        ((__nv_bfloat162*)(yh + (size_t)row*HDIM + 4*t))[0] = p0;
        ((__nv_bfloat162*)(yh + (size_t)row*HDIM + 4*t))[1] = p1;
        p0.x=l0; p0.y=l1; p1.x=l2; p1.y=l3;
        ((__nv_bfloat162*)(yl + (size_t)row*HDIM + 4*t))[0] = p0;
        ((__nv_bfloat162*)(yl + (size_t)row*HDIM + 4*t))[1] = p1;
    } else {
        ((float4*)(y + (size_t)row * HDIM))[t] = o;
    }
}

// ---------------- RoPE + split; q scaled by (1/8)*log2(e) for exp2-domain softmax ----
__global__ void rope_kernel(const float* __restrict__ qkv, int S) {
    int idx = blockIdx.x * blockDim.x + threadIdx.x;
    if (idx >= S * NHEAD * 32) return;
    int p    = idx & 31;
    int head = (idx >> 5) & (NHEAD - 1);
    int s    = idx >> 9;
    float c  = g_cos[s * 32 + p];
    float sn = g_sin[s * 32 + p];
    size_t src = (size_t)s * (3 * HDIM) + head * HEADD + 2 * p;
    size_t dst = (size_t)s * HDIM + head * HEADD + 2 * p;
    const float QSC = 0.125f * 1.4426950408889634f;
    float a, b, r0, r1;
    __nv_bfloat16 h0,h1,l0,l1;
    __nv_bfloat162 hp, lp;

    a = qkv[src]; b = qkv[src + 1];
    r0 = (a * c - b * sn) * QSC;
    r1 = (a * sn + b * c) * QSC;
    split_bf16(r0, h0, l0); split_bf16(r1, h1, l1);
    hp.x=h0; hp.y=h1; lp.x=l0; lp.y=l1;
    *(__nv_bfloat162*)(g_qhh + dst) = hp;
    *(__nv_bfloat162*)(g_qll + dst) = lp;

    a = qkv[src + HDIM]; b = qkv[src + HDIM + 1];
    r0 = a * c - b * sn;
    r1 = a * sn + b * c;
    split_bf16(r0, h0, l0); split_bf16(r1, h1, l1);
    hp.x=h0; hp.y=h1; lp.x=l0; lp.y=l1;
    *(__nv_bfloat162*)(g_khh + dst) = hp;
    *(__nv_bfloat162*)(g_kll + dst) = lp;

    a = qkv[src + 2*HDIM]; b = qkv[src + 2*HDIM + 1];
    split_bf16(a, h0, l0); split_bf16(b, h1, l1);
    hp.x=h0; hp.y=h1; lp.x=l0; lp.y=l1;
    *(__nv_bfloat162*)(g_vhh + dst) = hp;
    *(__nv_bfloat162*)(g_vll + dst) = lp;
}

// =================== tcgen05 bf16x3 GEMM (sm_103a cubin only) ===================
#define TC_IDESC 0x8400490u
#define TC_NT 256
#define TC_STAGE 98304
#define TC_SMEM (1024 + 2 * TC_STAGE)
#define TC_DESC(addr) ((2ull << 61) | (1ull << 46) | (64ull << 32) | (1ull << 16) \
                       | (((uint64_t)((addr) >> 4)) & 0x3FFF))

// ----- TMA variant (R8 proven loop): 4 UTMALDG per chunk, single-warp control ----
template<int EPI>
__global__ void __launch_bounds__(256, 1)
gemm_tc_tma(const __grid_constant__ CUtensorMap tAh, const __grid_constant__ CUtensorMap tAl,
            const __grid_constant__ CUtensorMap tBh, const __grid_constant__ CUtensorMap tBl,
            float* __restrict__ C, __nv_bfloat16* __restrict__ Ch, __nv_bfloat16* __restrict__ Cl,
            const float* __restrict__ bias, const float* __restrict__ res,
            int Nt, int Kt)
{
#if TC_OK
    extern __shared__ char tsm[];
    uint32_t sb  = (uint32_t)__cvta_generic_to_shared(tsm);
    int tid  = threadIdx.x;
    int wid  = tid >> 5;
    int lane = tid & 31;

    int m0 = blockIdx.y * 128;
    int n0 = blockIdx.x * TC_NT;

    uint32_t mf0 = sb + 8,  mf1 = sb + 16;
    uint32_t md0 = sb + 24, md1 = sb + 32;
    uint32_t st0 = sb + 1024, st1 = sb + 1024 + TC_STAGE;

    if (wid == 0) {
        tc_alloc(sb, TC_NT);
        tc_relinq();
    }
    if (tid == 0) {
        mbar_init(mf0, 1); mbar_init(mf1, 1);
        mbar_init(md0, 1); mbar_init(md1, 1);
    }
    __syncthreads();
    uint32_t tmem;
    asm volatile("ld.shared.b32 %0, [%1];" : "=r"(tmem) : "r"(sb));

    int NC = Kt >> 6;

    if (wid == 0) {
        if (elect_one()) {
            mbar_expect_tx(mf0, TC_STAGE);
            tma2d(st0,         &tAh, 0, m0, mf0);
            tma2d(st0 + 16384, &tAl, 0, m0, mf0);
            tma2d(st0 + 32768, &tBh, 0, n0, mf0);
            tma2d(st0 + 65536, &tBl, 0, n0, mf0);
            mbar_expect_tx(mf1, TC_STAGE);
            tma2d(st1,         &tAh, 64, m0, mf1);
            tma2d(st1 + 16384, &tAl, 64, m0, mf1);
            tma2d(st1 + 32768, &tBh, 64, n0, mf1);
            tma2d(st1 + 65536, &tBl, 64, n0, mf1);
        }
        uint32_t pf0 = 0, pf1 = 0, pd0 = 0, pd1 = 0;
        for (int i = 0; i < NC; i++) {
            int s = i & 1;
            uint32_t stb = s ? st1 : st0;
            if (s == 0) { mbar_wait(mf0, pf0 & 1); pf0++; }
            else        { mbar_wait(mf1, pf1 & 1); pf1++; }
            if (elect_one()) {
                uint64_t adh = TC_DESC(stb);
                uint64_t adl = TC_DESC(stb + 16384);
                uint64_t bdh = TC_DESC(stb + 32768);
                uint64_t bdl = TC_DESC(stb + 65536);
                #pragma unroll
                for (int ks = 0; ks < 4; ks++) {
                    tc_mma(tmem, adh + ks*2, bdh + ks*2, TC_IDESC, (i | ks) ? 1u : 0u);
                    tc_mma(tmem, adl + ks*2, bdh + ks*2, TC_IDESC, 1u);
                    tc_mma(tmem, adh + ks*2, bdl + ks*2, TC_IDESC, 1u);
                }
                tc_commit(s ? md1 : md0);
            }
            if (i + 2 < NC) {
                if (s == 0) { mbar_wait(md0, pd0 & 1); pd0++; }
                else        { mbar_wait(md1, pd1 & 1); pd1++; }
                if (elect_one()) {
                    int k0 = (i + 2) << 6;
                    uint32_t mf = s ? mf1 : mf0;
                    mbar_expect_tx(mf, TC_STAGE);
                    tma2d(stb,         &tAh, k0, m0, mf);
                    tma2d(stb + 16384, &tAl, k0, m0, mf);
                    tma2d(stb + 32768, &tBh, k0, n0, mf);
                    tma2d(stb + 65536, &tBl, k0, n0, mf);
                }
            }
        }
        mbar_wait(md0, pd0 & 1);
        mbar_wait(md1, pd1 & 1);
    }
    __syncthreads();
    tc_fence_after();

    int rowl  = (wid & 3) * 32 + lane;
    int halfc = (wid >> 2) * 128;
    size_t mg = (size_t)(m0 + rowl);
    #pragma unroll
    for (int cc = 0; cc < 4; cc++) {
        int c0 = halfc + cc * 32;
        uint32_t r[32];
        ldtm_x32(r, tmem + c0);
        tc_wait_ld();
        int ng = n0 + c0;
        if (EPI == 2) {
            #pragma unroll
            for (int j = 0; j < 32; j += 2) {
                float v0 = __uint_as_float(r[j])   + bias[ng + j];
                float v1 = __uint_as_float(r[j+1]) + bias[ng + j + 1];
                v0 = 0.5f * v0 * (1.0f + erff(v0 * 0.7071067811865476f));
                v1 = 0.5f * v1 * (1.0f + erff(v1 * 0.7071067811865476f));
                __nv_bfloat16 h0,h1,l0,l1;
                split_bf16(v0,h0,l0); split_bf16(v1,h1,l1);
                __nv_bfloat162 p;
                p.x=h0; p.y=h1; *(__nv_bfloat162*)(Ch + mg*Nt + ng + j) = p;
                p.x=l0; p.y=l1; *(__nv_bfloat162*)(Cl + mg*Nt + ng + j) = p;
            }
        } else {
            #pragma unroll
            for (int j = 0; j < 8; j++) {
                float4 v;
                v.x = __uint_as_float(r[4*j]);
                v.y = __uint_as_float(r[4*j+1]);
                v.z = __uint_as_float(r[4*j+2]);
                v.w = __uint_as_float(r[4*j+3]);
                if (EPI == 3) {
                    float4 bv = *(const float4*)(bias + ng + 4*j);
                    v.x += bv.x; v.y += bv.y; v.z += bv.z; v.w += bv.w;
                }
                if (EPI == 1 || EPI == 3) {
                    float4 rv = *(const float4*)(res + mg*Nt + ng + 4*j);
                    v.x += rv.x; v.y += rv.y; v.z += rv.z; v.w += rv.w;
                }
                *(float4*)(C + mg*Nt + ng + 4*j) = v;
            }
        }
    }

    __syncthreads();
    if (tid == 0) { mbar_inval(mf0); mbar_inval(mf1); mbar_inval(md0); mbar_inval(md1); }
    __syncthreads();
    if (wid == 0) tc_dealloc(tmem, TC_NT);
#endif
}

// =================== tcgen05 flash attention, 2 CTAs/SM (97KB smem, VT overlays K) ====
// CTA = (q-tile 128, head), 128 threads. S,O in TMEM. After QK(i) completes, V(i) is
// transposed INTO the stage's K region (dead), eliminating the separate VT buffer.
#define ATC_Q    1024
#define ATC_ST0  (ATC_Q + 32768)
#define ATC_ST1  (ATC_ST0 + 32768)
#define ATC_SMEM (ATC_ST1 + 32768)      // 99328 B -> 2 CTAs/SM
#define ATC_IDESC 0x8100490u            // f16 kind, M=128, N=64

__global__ void __launch_bounds__(128, 2)
attn_tc(const __grid_constant__ CUtensorMap mQh, const __grid_constant__ CUtensorMap mQl,
        const __grid_constant__ CUtensorMap mKh, const __grid_constant__ CUtensorMap mKl,
        const __grid_constant__ CUtensorMap mVh, const __grid_constant__ CUtensorMap mVl,
        __nv_bfloat16* __restrict__ oh, __nv_bfloat16* __restrict__ ol, int S)
{
#if TC_OK
    extern __shared__ char asm_[];
    uint32_t sb = (uint32_t)__cvta_generic_to_shared(asm_);
    int tid  = threadIdx.x;
    int wid  = tid >> 5;
    int lane = tid & 31;
    int head = blockIdx.y;
    int q0   = blockIdx.x * 128;
    int hx   = head * HEADD;

    int segs = 0, sege = S;
    int ng = g_nseg;
    for (int g = 0; g < ng; g++) {
        if (q0 >= g_bounds[g] && q0 < g_bounds[g+1]) {
            segs = g_bounds[g]; sege = g_bounds[g+1]; break;
        }
    }
    int niter = (sege - segs) >> 6;

    uint32_t mf[2] = { sb + 8, sb + 16 };
    uint32_t mbs = sb + 24, mbo = sb + 32;
    uint32_t stg[2] = { sb + ATC_ST0, sb + ATC_ST1 };

    if (wid == 0) { tc_alloc(sb, 256); tc_relinq(); }
    if (tid == 0) {
        mbar_init(mf[0], 1); mbar_init(mf[1], 1);
        mbar_init(mbs, 1); mbar_init(mbo, 1);
    }
    __syncthreads();
    uint32_t tmem;
    asm volatile("ld.shared.b32 %0, [%1];" : "=r"(tmem) : "r"(sb));
    uint32_t tm_s = tmem, tm_o = tmem + 64, tm_ph = tmem + 128, tm_pl = tmem + 160;
    uint32_t woff = (uint32_t)wid << 21;

    // prologue TMA: Q + tile0 on mf0, tile1 on mf1 (both stages initially free)
    if (tid == 0) {
        mbar_expect_tx(mf[0], 32768 + 32768);
        tma2d(sb + ATC_Q,          &mQh, hx, q0, mf[0]);
        tma2d(sb + ATC_Q + 16384,  &mQl, hx, q0, mf[0]);
        tma2d(stg[0],              &mKh, hx, segs, mf[0]);
        tma2d(stg[0] + 8192,       &mKl, hx, segs, mf[0]);
        tma2d(stg[0] + 16384,      &mVh, hx, segs, mf[0]);
        tma2d(stg[0] + 24576,      &mVl, hx, segs, mf[0]);
        if (niter > 1) {
            mbar_expect_tx(mf[1], 32768);
            tma2d(stg[1],          &mKh, hx, segs + 64, mf[1]);
            tma2d(stg[1] + 8192,   &mKl, hx, segs + 64, mf[1]);
            tma2d(stg[1] + 16384,  &mVh, hx, segs + 64, mf[1]);
            tma2d(stg[1] + 24576,  &mVl, hx, segs + 64, mf[1]);
        }
    }

    uint64_t qdh = TC_DESC(sb + ATC_Q);
    uint64_t qdl = TC_DESC(sb + ATC_Q + 16384);

    float mrow = -1e30f, lrow = 0.f;
    uint32_t pf[2] = {0, 0};
    uint32_t ph_s = 0, ph_o = 0;

    for (int i = 0; i < niter; i++) {
        int s = i & 1, s1 = s ^ 1;
        // 1. wait tile i
        mbar_wait(mf[s], pf[s] & 1); pf[s]++;
        // 2. issue QK(i) reading K from stg[s]
        if (wid == 0) {
            tc_fence_after();
            if (elect_one()) {
                uint64_t kdh = TC_DESC(stg[s]);
                uint64_t kdl = TC_DESC(stg[s] + 8192);
                #pragma unroll
                for (int ks = 0; ks < 4; ks++) {
                    tc_mma(tm_s, qdh + ks*2, kdh + ks*2, ATC_IDESC, ks ? 1u : 0u);
                    tc_mma(tm_s, qdl + ks*2, kdh + ks*2, ATC_IDESC, 1u);
                    tc_mma(tm_s, qdh + ks*2, kdl + ks*2, ATC_IDESC, 1u);
                }
                tc_commit(mbs);
            }
        }
        // 3. wait PV(i-1) (frees stage s1: its VT and V regions) — overlaps QK(i)
        if (i > 0) { mbar_wait(mbo, ph_o & 1); ph_o++; tc_fence_after(); }
        // 4. prefetch tile i+1 into stage s1 (only valid after PV(i-1) done)
        if (i >= 1 && i + 1 < niter && tid == 0) {
            int k0 = segs + (i + 1) * 64;
            mbar_expect_tx(mf[s1], 32768);
            tma2d(stg[s1],         &mKh, hx, k0, mf[s1]);
            tma2d(stg[s1] + 8192,  &mKl, hx, k0, mf[s1]);
            tma2d(stg[s1] + 16384, &mVh, hx, k0, mf[s1]);
            tma2d(stg[s1] + 24576, &mVl, hx, k0, mf[s1]);
        }
        // 5. wait QK(i) done — K region of stage s now dead
        mbar_wait(mbs, ph_s & 1); ph_s++;
        tc_fence_after();
        // 6. transpose V(i) into the K region of stage s (VT overlay)
        {
            uint32_t stV = stg[s] + 16384;
            int r8 = lane & 7;
            #pragma unroll
            for (int g = 0; g < 4; g++) {
                int t = wid * 16 + g * 4 + (lane >> 3);
                int kr = t >> 3, dc = t & 7;
                int srow = kr * 8 + r8;
                uint32_t saddr = stV + srow * 128 + (uint32_t)(((dc ^ (srow & 7))) << 4);
                int drow = dc * 8 + r8;
                uint32_t daddr = stg[s] + drow * 128 + (uint32_t)(((kr ^ (drow & 7))) << 4);
                uint32_t rr[4];
                ldm_x4_t(rr, saddr);
                stm_x4(daddr, rr);
                ldm_x4_t(rr, saddr + 8192);
                stm_x4(daddr + 8192, rr);
            }
        }
        fence_proxy_async_s();
        // 7. read S; per-lane online softmax (exp2 domain)
        float sv[64];
        ldtm_x32((uint32_t*)sv,      tm_s);
        ldtm_x32((uint32_t*)(sv+32), tm_s + 32);
        tc_wait_ld();
        float rmax = sv[0];
        #pragma unroll
        for (int j = 1; j < 64; j++) rmax = fmaxf(rmax, sv[j]);
        float mnew  = fmaxf(mrow, rmax);
        float alpha = ex2f(mrow - mnew);
        mrow = mnew;
        float sum = 0.f;
        #pragma unroll
        for (int j = 0; j < 64; j++) { sv[j] = ex2f(sv[j] - mnew); sum += sv[j]; }
        lrow = lrow * alpha + sum;
        uint32_t phr[32], plr[32];
        #pragma unroll
        for (int c = 0; c < 32; c++) phr[c] = pack_bf16_hi(sv[2*c], sv[2*c+1], plr[c]);
        sttm_x32(tm_ph + woff, phr);
        sttm_x32(tm_pl + woff, plr);
        tc_wait_st();
        // 8. O rescale by alpha
        if (i > 0) {
            float ov[64];
            ldtm_x32((uint32_t*)ov,      tm_o);
            ldtm_x32((uint32_t*)(ov+32), tm_o + 32);
            tc_wait_ld();
            #pragma unroll
            for (int j = 0; j < 64; j++) ov[j] *= alpha;
            sttm_x32(tm_o + woff,      (uint32_t*)ov);
            sttm_x32(tm_o + 32 + woff, (uint32_t*)(ov+32));
            tc_wait_st();
        }
        tc_fence_before();
        __syncthreads();
        // 9. PV(i): O += P * V^T (VT in stage s K region)
        if (wid == 0) {
            tc_fence_after();
            if (elect_one()) {
                uint64_t vtdh = TC_DESC(stg[s]);
                uint64_t vtdl = TC_DESC(stg[s] + 8192);
                #pragma unroll
                for (int ks = 0; ks < 4; ks++) {
                    tc_mma_ts(tm_o, tm_ph + ks*8, vtdh + ks*2, ATC_IDESC,
                              (i | ks) ? 1u : 0u);
                    tc_mma_ts(tm_o, tm_pl + ks*8, vtdh + ks*2, ATC_IDESC, 1u);
                    tc_mma_ts(tm_o, tm_ph + ks*8, vtdl + ks*2, ATC_IDESC, 1u);
                }
                tc_commit(mbo);
            }
        }
        __syncthreads();
    }

    mbar_wait(mbo, ph_o & 1);
    tc_fence_after();

    float ov[64];
    ldtm_x32((uint32_t*)ov,      tm_o);
    ldtm_x32((uint32_t*)(ov+32), tm_o + 32);
    tc_wait_ld();
    float il = 1.0f / lrow;
    size_t base = (size_t)(q0 + wid * 32 + lane) * HDIM + hx;
    #pragma unroll
    for (int c = 0; c < 32; c++) {
        float v0 = ov[2*c] * il, v1 = ov[2*c+1] * il;
        __nv_bfloat16 h0,h1,l0,l1;
        split_bf16(v0,h0,l0); split_bf16(v1,h1,l1);
        __nv_bfloat162 p;
        p.x=h0; p.y=h1; *(__nv_bfloat162*)(oh + base + 2*c) = p;
        p.x=l0; p.y=l1; *(__nv_bfloat162*)(ol + base + 2*c) = p;
    }

    __syncthreads();
    if (tid == 0) { mbar_inval(mf[0]); mbar_inval(mf[1]); mbar_inval(mbs); mbar_inval(mbo); }
    __syncthreads();
    if (wid == 0) tc_dealloc(tmem, 256);
#endif
}

// ---------------- FA2 mma.sync attention (fallback) ----------------
#define AST 72
#define ATILE (64 * AST)
#define ASTAGE (4 * ATILE * 2)
#define ATTN_SMEM_BYTES (2 * ASTAGE)

__global__ void __launch_bounds__(256) attn_kernel(
    const __nv_bfloat16* __restrict__ qh, const __nv_bfloat16* __restrict__ ql,
    const __nv_bfloat16* __restrict__ kh, const __nv_bfloat16* __restrict__ kl,
    const __nv_bfloat16* __restrict__ vh, const __nv_bfloat16* __restrict__ vl,
    __nv_bfloat16* __restrict__ oh, __nv_bfloat16* __restrict__ ol, int S)
{
    extern __shared__ char smraw[];
    uint32_t sb  = (uint32_t)__cvta_generic_to_shared(smraw);

    int head = blockIdx.y;
    int q0   = blockIdx.x * 128;
    int tid  = threadIdx.x;
    int lane = tid & 31;
    int wid  = tid >> 5;
    int grp  = lane >> 2;
    int tig  = lane & 3;

    int segs = 0, sege = S;
    int ng = g_nseg;
    for (int g = 0; g < ng; g++) {
        if (q0 >= g_bounds[g] && q0 < g_bounds[g+1]) {
            segs = g_bounds[g]; sege = g_bounds[g+1]; break;
        }
    }

    int qrow = q0 + wid * 16 + grp;
    uint32_t qfh[4][4], qfl[4][4];
    #pragma unroll
    for (int kc = 0; kc < 4; kc++) {
        #pragma unroll
        for (int i = 0; i < 4; i++) {
            int r = qrow + (i & 1) * 8;
            int c = kc * 16 + (i >> 1) * 8 + 2 * tig;
            size_t off = (size_t)r * HDIM + head * HEADD + c;
            qfh[kc][i] = *(const uint32_t*)(qh + off);
            qfl[kc][i] = *(const uint32_t*)(ql + off);
        }
    }

    float m0 = -1e30f, m1 = -1e30f, l0 = 0.f, l1 = 0.f;
    float oacc[8][4];
    #pragma unroll
    for (int j = 0; j < 8; j++)
        #pragma unroll
        for (int c = 0; c < 4; c++) oacc[j][c] = 0.f;

    int brow = (lane & 7) + ((lane & 16) >> 1), bcol = lane & 8;
    int vrow = lane & 15,  vcol = (lane >> 4) << 3;

    int f0 = tid,        r0_ = f0 >> 3, c80 = (f0 & 7) << 3;
    int f1 = tid + 256,  r1_ = f1 >> 3, c81 = (f1 & 7) << 3;
    uint32_t so0 = (uint32_t)(r0_ * AST + c80) * 2;
    uint32_t so1 = (uint32_t)(r1_ * AST + c81) * 2;

    int niter = (sege - segs) >> 6;

    {
        size_t gs0 = (size_t)(segs + r0_) * HDIM + head * HEADD + c80;
        size_t gs1 = (size_t)(segs + r1_) * HDIM + head * HEADD + c81;
        cp16(sb + so0,             kh + gs0); cp16(sb + so1,             kh + gs1);
        cp16(sb + ATILE*2 + so0,   kl + gs0); cp16(sb + ATILE*2 + so1,   kl + gs1);
        cp16(sb + 2*ATILE*2 + so0, vh + gs0); cp16(sb + 2*ATILE*2 + so1, vh + gs1);
        cp16(sb + 3*ATILE*2 + so0, vl + gs0); cp16(sb + 3*ATILE*2 + so1, vl + gs1);
        asm volatile("cp.async.commit_group;" ::);
    }

    for (int it = 0; it < niter; it++) {
        if (it + 1 < niter) {
            int k0n = segs + (it + 1) * 64;
            uint32_t stb = sb + ((it + 1) & 1) * ASTAGE;
            size_t gs0 = (size_t)(k0n + r0_) * HDIM + head * HEADD + c80;
            size_t gs1 = (size_t)(k0n + r1_) * HDIM + head * HEADD + c81;
            cp16(stb + so0,             kh + gs0); cp16(stb + so1,             kh + gs1);
            cp16(stb + ATILE*2 + so0,   kl + gs0); cp16(stb + ATILE*2 + so1,   kl + gs1);
            cp16(stb + 2*ATILE*2 + so0, vh + gs0); cp16(stb + 2*ATILE*2 + so1, vh + gs1);
            cp16(stb + 3*ATILE*2 + so0, vl + gs0); cp16(stb + 3*ATILE*2 + so1, vl + gs1);
            asm volatile("cp.async.commit_group;" ::);
            asm volatile("cp.async.wait_group 1;" ::);
        } else {
            asm volatile("cp.async.wait_group 0;" ::);
        }
        __syncthreads();

        uint32_t bKh = sb + (it & 1) * ASTAGE;
        uint32_t bKl = bKh + ATILE * 2;
        uint32_t bVh = bKh + 2 * ATILE * 2;
        uint32_t bVl = bKh + 3 * ATILE * 2;

        float sacc[8][4];
        #pragma unroll
        for (int j = 0; j < 8; j++)
            #pragma unroll
            for (int c = 0; c < 4; c++) sacc[j][c] = 0.f;
        #pragma unroll
        for (int kc = 0; kc < 4; kc++) {
            int kk = kc << 4;
            uint32_t bb[8][2];
            #pragma unroll
            for (int jj = 0; jj < 4; jj++) {
                uint32_t rb = ((jj*16 + brow) * AST + kk + bcol) * 2;
                uint32_t tr[4];
                ldm_x4(tr, bKh + rb);
                bb[2*jj][0]=tr[0]; bb[2*jj][1]=tr[1]; bb[2*jj+1][0]=tr[2]; bb[2*jj+1][1]=tr[3];
            }
            #pragma unroll
            for (int j = 0; j < 8; j++) {
                mma_bf16(sacc[j], qfh[kc], bb[j]);
                mma_bf16(sacc[j], qfl[kc], bb[j]);
            }
            #pragma unroll
            for (int jj = 0; jj < 4; jj++) {
                uint32_t rb = ((jj*16 + brow) * AST + kk + bcol) * 2;
                uint32_t tr[4];
                ldm_x4(tr, bKl + rb);
                bb[2*jj][0]=tr[0]; bb[2*jj][1]=tr[1]; bb[2*jj+1][0]=tr[2]; bb[2*jj+1][1]=tr[3];
            }
            #pragma unroll
            for (int j = 0; j < 8; j++)
                mma_bf16(sacc[j], qfh[kc], bb[j]);
        }

        float r0 = -1e30f, r1 = -1e30f;
        #pragma unroll
        for (int j = 0; j < 8; j++) {
            r0 = fmaxf(r0, fmaxf(sacc[j][0], sacc[j][1]));
            r1 = fmaxf(r1, fmaxf(sacc[j][2], sacc[j][3]));
        }
        r0 = fmaxf(r0, __shfl_xor_sync(0xffffffffu, r0, 1));
        r0 = fmaxf(r0, __shfl_xor_sync(0xffffffffu, r0, 2));
        r1 = fmaxf(r1, __shfl_xor_sync(0xffffffffu, r1, 1));
        r1 = fmaxf(r1, __shfl_xor_sync(0xffffffffu, r1, 2));
        float mn0 = fmaxf(m0, r0), mn1 = fmaxf(m1, r1);
        float al0 = ex2f(m0 - mn0), al1 = ex2f(m1 - mn1);
        float sum0 = 0.f, sum1 = 0.f;
        #pragma unroll
        for (int j = 0; j < 8; j++) {
            sacc[j][0] = ex2f(sacc[j][0] - mn0); sum0 += sacc[j][0];
            sacc[j][1] = ex2f(sacc[j][1] - mn0); sum0 += sacc[j][1];
            sacc[j][2] = ex2f(sacc[j][2] - mn1); sum1 += sacc[j][2];
            sacc[j][3] = ex2f(sacc[j][3] - mn1); sum1 += sacc[j][3];
        }
        sum0 += __shfl_xor_sync(0xffffffffu, sum0, 1);
        sum0 += __shfl_xor_sync(0xffffffffu, sum0, 2);
        sum1 += __shfl_xor_sync(0xffffffffu, sum1, 1);
        sum1 += __shfl_xor_sync(0xffffffffu, sum1, 2);
        l0 = l0 * al0 + sum0;
        l1 = l1 * al1 + sum1;
        m0 = mn0; m1 = mn1;
        #pragma unroll
        for (int j = 0; j < 8; j++) {
            oacc[j][0] *= al0; oacc[j][1] *= al0;
            oacc[j][2] *= al1; oacc[j][3] *= al1;
        }

        #pragma unroll
        for (int kc = 0; kc < 4; kc++) {
            uint32_t pfh[4], pfl[4];
            pfh[0] = pack_bf16_hi(sacc[2*kc][0],   sacc[2*kc][1],   pfl[0]);
            pfh[1] = pack_bf16_hi(sacc[2*kc][2],   sacc[2*kc][3],   pfl[1]);
            pfh[2] = pack_bf16_hi(sacc[2*kc+1][0], sacc[2*kc+1][1], pfl[2]);
            pfh[3] = pack_bf16_hi(sacc[2*kc+1][2], sacc[2*kc+1][3], pfl[3]);
            uint32_t bb[8][2];
            #pragma unroll
            for (int jn = 0; jn < 4; jn++) {
                uint32_t rb = ((kc*16 + vrow) * AST + jn*16 + vcol) * 2;
                uint32_t tr[4];
                ldm_x4_t(tr, bVh + rb);
                bb[2*jn][0]=tr[0]; bb[2*jn][1]=tr[1]; bb[2*jn+1][0]=tr[2]; bb[2*jn+1][1]=tr[3];
            }
            #pragma unroll
            for (int j = 0; j < 8; j++) {
                mma_bf16(oacc[j], pfh, bb[j]);
                mma_bf16(oacc[j], pfl, bb[j]);
            }
            #pragma unroll
            for (int jn = 0; jn < 4; jn++) {
                uint32_t rb = ((kc*16 + vrow) * AST + jn*16 + vcol) * 2;
                uint32_t tr[4];
                ldm_x4_t(tr, bVl + rb);
                bb[2*jn][0]=tr[0]; bb[2*jn][1]=tr[1]; bb[2*jn+1][0]=tr[2]; bb[2*jn+1][1]=tr[3];
            }
            #pragma unroll
            for (int j = 0; j < 8; j++)
                mma_bf16(oacc[j], pfh, bb[j]);
        }
        __syncthreads();
    }

    float il0 = 1.0f / l0, il1 = 1.0f / l1;
    #pragma unroll
    for (int j = 0; j < 8; j++) {
        int d = j * 8 + 2 * tig;
        float v0 = oacc[j][0] * il0, v1 = oacc[j][1] * il0;
        float v2 = oacc[j][2] * il1, v3 = oacc[j][3] * il1;
        __nv_bfloat16 h0,h1,h2,h3,lo0,lo1,lo2,lo3;
        split_bf16(v0,h0,lo0); split_bf16(v1,h1,lo1);
        split_bf16(v2,h2,lo2); split_bf16(v3,h3,lo3);
        size_t p0 = (size_t)qrow * HDIM + head * HEADD + d;
        size_t p1 = (size_t)(qrow + 8) * HDIM + head * HEADD + d;
        __nv_bfloat162 p;
        p.x=h0;  p.y=h1;  *(__nv_bfloat162*)(oh + p0) = p;
        p.x=h2;  p.y=h3;  *(__nv_bfloat162*)(oh + p1) = p;
        p.x=lo0; p.y=lo1; *(__nv_bfloat162*)(ol + p0) = p;
        p.x=lo2; p.y=lo3; *(__nv_bfloat162*)(ol + p1) = p;
    }
}

// ---------------- launch ----------------
typedef CUresult (*PFN_tmap_enc)(
    CUtensorMap*, CUtensorMapDataType, cuuint32_t, void*,
    const cuuint64_t*, const cuuint64_t*, const cuuint32_t*, const cuuint32_t*,
    CUtensorMapInterleave, CUtensorMapSwizzle, CUtensorMapL2promotion, CUtensorMapFloatOOBfill);

static bool make_map2d(PFN_tmap_enc fn, CUtensorMap* m, void* base,
                       uint64_t d0, uint64_t d1, uint32_t b0, uint32_t b1) {
    cuuint64_t dims[2]    = {d0, d1};
    cuuint64_t strides[1] = {d0 * 2};
    cuuint32_t box[2]     = {b0, b1};
    cuuint32_t es[2]      = {1, 1};
    return fn(m, CU_TENSOR_MAP_DATA_TYPE_BFLOAT16, 2, base, dims, strides, box, es,
              CU_TENSOR_MAP_INTERLEAVE_NONE, CU_TENSOR_MAP_SWIZZLE_128B,
              CU_TENSOR_MAP_L2_PROMOTION_L2_128B,
              CU_TENSOR_MAP_FLOAT_OOB_FILL_NONE) == CUDA_SUCCESS;
}

extern "C" void kernel_launch(void* const* d_in, const int* in_sizes, int n_in,
                              void* d_out, int out_size) {
    const float* hidden = (const float*)d_in[0];
    const int*   gthw   = (const int*)  d_in[1];
    const float* ln0_g  = (const float*)d_in[2];
    const float* ln0_b  = (const float*)d_in[3];
    const float* wqkv   = (const float*)d_in[4];
    const float* wo     = (const float*)d_in[5];
    const float* ln1_g  = (const float*)d_in[6];
    const float* ln1_b  = (const float*)d_in[7];
    const float* fc0_w  = (const float*)d_in[8];
    const float* fc0_b  = (const float*)d_in[9];
    const float* fc1_w  = (const float*)d_in[10];
    const float* fc1_b  = (const float*)d_in[11];
    const float* fln_g  = (const float*)d_in[12];
    const float* fln_b  = (const float*)d_in[13];

    int S      = in_sizes[0] / HDIM;
    int ngrids = in_sizes[1] / 3;

    float *xp, *qkvp;
    __nv_bfloat16 *hh, *hl, *ohp, *olp, *qhh, *qll, *khh, *kll, *vhh, *vll, *mh, *ml, *wh, *wl;
    cudaGetSymbolAddress((void**)&xp,   g_x);
    cudaGetSymbolAddress((void**)&qkvp, g_qkv);
    cudaGetSymbolAddress((void**)&hh,   g_hh);
    cudaGetSymbolAddress((void**)&hl,   g_hl);
    cudaGetSymbolAddress((void**)&ohp,  g_oh);
    cudaGetSymbolAddress((void**)&olp,  g_ol);
    cudaGetSymbolAddress((void**)&qhh,  g_qhh);
    cudaGetSymbolAddress((void**)&qll,  g_qll);
    cudaGetSymbolAddress((void**)&khh,  g_khh);
    cudaGetSymbolAddress((void**)&kll,  g_kll);
    cudaGetSymbolAddress((void**)&vhh,  g_vhh);
    cudaGetSymbolAddress((void**)&vll,  g_vll);
    cudaGetSymbolAddress((void**)&mh,   g_mh);
    cudaGetSymbolAddress((void**)&ml,   g_ml);
    cudaGetSymbolAddress((void**)&wh,   g_wh);
    cudaGetSymbolAddress((void**)&wl,   g_wl);

    cudaFuncAttributes pa;
    bool use_tc = false;
    if (cudaFuncGetAttributes(&pa, probe_kernel) == cudaSuccess)
        use_tc = (pa.sharedSizeBytes < 64);

    PFN_tmap_enc enc = nullptr;
    {
        void* fp = nullptr;
        cudaDriverEntryPointQueryResult qr;
        if (cudaGetDriverEntryPoint("cuTensorMapEncodeTiled", &fp,
                                    cudaEnableDefault, &qr) == cudaSuccess &&
            qr == cudaDriverEntryPointSuccess)
            enc = (PFN_tmap_enc)fp;
    }
    bool use_tma = use_tc && (enc != nullptr);

    cudaFuncSetAttribute(attn_kernel, cudaFuncAttributeMaxDynamicSharedMemorySize, ATTN_SMEM_BYTES);
    if (use_tma) {
        cudaFuncSetAttribute(gemm_tc_tma<0>, cudaFuncAttributeMaxDynamicSharedMemorySize, TC_SMEM);
        cudaFuncSetAttribute(gemm_tc_tma<1>, cudaFuncAttributeMaxDynamicSharedMemorySize, TC_SMEM);
        cudaFuncSetAttribute(gemm_tc_tma<2>, cudaFuncAttributeMaxDynamicSharedMemorySize, TC_SMEM);
        cudaFuncSetAttribute(gemm_tc_tma<3>, cudaFuncAttributeMaxDynamicSharedMemorySize, TC_SMEM);
        cudaFuncSetAttribute(attn_tc, cudaFuncAttributeMaxDynamicSharedMemorySize, ATC_SMEM);
    }

    const size_t SZ_QKV = (size_t)2 * 3 * HDIM * HDIM;
    const size_t SZ_WO  = (size_t)2 * HDIM * HDIM;
    const size_t SZ_FC0 = (size_t)2 * MDIM * HDIM;
    const size_t OFF_QKV = 0;
    const size_t OFF_WO  = OFF_QKV + SZ_QKV;
    const size_t OFF_FC0 = OFF_WO + SZ_WO;
    const size_t OFF_FC1 = OFF_FC0 + SZ_FC0;

    CUtensorMap mQh, mQl, mKh, mKl, mVh, mVl;
    bool attn_maps_ok = false;
    if (use_tma) {
        attn_maps_ok = make_map2d(enc, &mQh, qhh, HDIM, (uint64_t)S, 64, 128)
                    && make_map2d(enc, &mQl, qll, HDIM, (uint64_t)S, 64, 128)
                    && make_map2d(enc, &mKh, khh, HDIM, (uint64_t)S, 64, 64)
                    && make_map2d(enc, &mKl, kll, HDIM, (uint64_t)S, 64, 64)
                    && make_map2d(enc, &mVh, vhh, HDIM, (uint64_t)S, 64, 64)
                    && make_map2d(enc, &mVl, vll, HDIM, (uint64_t)S, 64, 64);
    }

    auto launch_gemm = [&](int epi, __nv_bfloat16* Ah, __nv_bfloat16* Al,
                           __nv_bfloat16* Bh, __nv_bfloat16* Bl,
                           float* C, __nv_bfloat16* Ch, __nv_bfloat16* Cl,
                           const float* bias, const float* res, int Nt, int Kt) {
        CUtensorMap tAh, tAl, tBh, tBl;
        bool ok = use_tma
               && make_map2d(enc, &tAh, Ah, (uint64_t)Kt, (uint64_t)S,  64, 128)
               && make_map2d(enc, &tAl, Al, (uint64_t)Kt, (uint64_t)S,  64, 128)
               && make_map2d(enc, &tBh, Bh, (uint64_t)Kt, (uint64_t)Nt, 64, 256)
               && make_map2d(enc, &tBl, Bl, (uint64_t)Kt, (uint64_t)Nt, 64, 256);
        dim3 grid(Nt / TC_NT, S / 128);
        if (ok) {
            switch (epi) {
            case 0: gemm_tc_tma<0><<<grid, 256, TC_SMEM>>>(tAh,tAl,tBh,tBl,C,Ch,Cl,bias,res,Nt,Kt); return;
            case 1: gemm_tc_tma<1><<<grid, 256, TC_SMEM>>>(tAh,tAl,tBh,tBl,C,Ch,Cl,bias,res,Nt,Kt); return;
            case 2: gemm_tc_tma<2><<<grid, 256, TC_SMEM>>>(tAh,tAl,tBh,tBl,C,Ch,Cl,bias,res,Nt,Kt); return;
            default: gemm_tc_tma<3><<<grid, 256, TC_SMEM>>>(tAh,tAl,tBh,tBl,C,Ch,Cl,bias,res,Nt,Kt); return;
            }
        }
    };

    {
        int n1 = (int)(SZ_QKV / 4), n2 = (int)(SZ_WO / 4);
        conv2_kernel<<<(n1 + n2 + 255) / 256, 256>>>(
            wqkv, wh + OFF_QKV, wl + OFF_QKV, n1,
            wo,   wh + OFF_WO,  wl + OFF_WO,  n2);
        int n3 = (int)(SZ_FC0 / 4);
        conv2_kernel<<<(2 * n3 + 255) / 256, 256>>>(
            fc0_w, wh + OFF_FC0, wl + OFF_FC0, n3,
            fc1_w, wh + OFF_FC1, wl + OFF_FC1, n3);
    }

    const float* xsrc = hidden;
    for (int l = 0; l < 2; l++) {
        size_t wq  = OFF_QKV + (size_t)l * 3 * HDIM * HDIM;
        size_t w05 = OFF_WO  + (size_t)l * HDIM * HDIM;
        size_t w0  = OFF_FC0 + (size_t)l * MDIM * HDIM;
        size_t w1  = OFF_FC1 + (size_t)l * HDIM * MDIM;

        ln_kernel<1><<<S, 256>>>(xsrc, ln0_g + l * HDIM, ln0_b + l * HDIM, nullptr, hh, hl);
        launch_gemm(0, hh, hl, wh + wq, wl + wq, qkvp, nullptr, nullptr, nullptr, nullptr,
                    3 * HDIM, HDIM);
        if (l == 0) {
            setup_kernel<<<1, 32>>>(gthw, ngrids);
            cossin_kernel<<<(S * 32 + 255) / 256, 256>>>(gthw, ngrids, S);
        }
        rope_kernel<<<(S * NHEAD * 32 + 255) / 256, 256>>>(qkvp, S);
        if (attn_maps_ok) {
            attn_tc<<<dim3(S / 128, NHEAD), 128, ATC_SMEM>>>(
                mQh, mQl, mKh, mKl, mVh, mVl, ohp, olp, S);
        } else {
            attn_kernel<<<dim3(S / 128, NHEAD), 256, ATTN_SMEM_BYTES>>>(
                qhh, qll, khh, kll, vhh, vll, ohp, olp, S);
        }
        launch_gemm(1, ohp, olp, wh + w05, wl + w05, xp, nullptr, nullptr, nullptr, xsrc,
                    HDIM, HDIM);
        ln_kernel<1><<<S, 256>>>(xp, ln1_g + l * HDIM, ln1_b + l * HDIM, nullptr, hh, hl);
        launch_gemm(2, hh, hl, wh + w0, wl + w0, nullptr, mh, ml, fc0_b + l * MDIM, nullptr,
                    MDIM, HDIM);
        launch_gemm(3, mh, ml, wh + w1, wl + w1, xp, nullptr, nullptr, fc1_b + l * HDIM, xp,
                    HDIM, MDIM);
        xsrc = xp;
    }
    ln_kernel<0><<<S, 256>>>(xp, fln_g, fln_b, (float*)d_out, nullptr, nullptr);
}